// round 2
// baseline (speedup 1.0000x reference)
#include <cuda_runtime.h>

#define Bn 32768
#define Fn 512
#define En 8
#define Hn 128
#define An 256
#define Tn 8
#define HCn 32

#define TB 128   // rows per tile
#define KB 32    // K chunk
#define XP 36    // padded row stride for x tile (float), 16B-aligned, conflict-avoiding
#define HP 129   // padded row stride for hT tile

// Routing scratch (allocation-free per harness rules)
__device__ int g_acnt[En];
__device__ int g_ccnt[Tn];
__device__ int g_alist[En * Bn];
__device__ int g_clist[Tn * Bn];

__global__ void zero_kernel() {
    int t = threadIdx.x;
    if (t < En) g_acnt[t] = 0;
    if (t < Tn) g_ccnt[t] = 0;
}

__global__ void route_kernel(const int* __restrict__ commands,
                             const int* __restrict__ tasks) {
    __shared__ int scA[En], scC[Tn], baseA[En], baseC[Tn];
    int tid = threadIdx.x;
    if (tid < En) scA[tid] = 0;
    if (tid < Tn) scC[tid] = 0;
    __syncthreads();
    int b = blockIdx.x * blockDim.x + tid;
    int e = 0, t = 0, pa = 0, pc = 0;
    if (b < Bn) {
        e = commands[b];
        pa = atomicAdd(&scA[e], 1);
        t = tasks[b];
        pc = atomicAdd(&scC[t], 1);
    }
    __syncthreads();
    if (tid < En) baseA[tid] = atomicAdd(&g_acnt[tid], scA[tid]);
    if (tid < Tn) baseC[tid] = atomicAdd(&g_ccnt[tid], scC[tid]);
    __syncthreads();
    if (b < Bn) {
        g_alist[e * Bn + baseA[e] + pa] = b;
        g_clist[t * Bn + baseC[t] + pc] = b;
    }
}

// ---------------------------------------------------------------------------
// Actor: per (expert, 128-row tile): h = relu(X*W1+b1) [128x128],
// scores = h*W2+b2 [128x256] kept in registers in two 128-col halves with
// online softmax stats. Writes out[:,0] (lp_chosen) and out[:,2] (neg_entropy).
// ---------------------------------------------------------------------------
extern "C" __global__ void __launch_bounds__(256)
actor_kernel(const float* __restrict__ x, const int* __restrict__ actions,
             const float* __restrict__ W1, const float* __restrict__ b1,
             const float* __restrict__ W2, const float* __restrict__ b2,
             float* __restrict__ out) {
    int e = blockIdx.y;
    int cnt = g_acnt[e];
    int r0 = blockIdx.x * TB;
    if (r0 >= cnt) return;

    extern __shared__ float smem[];
    float* hs = smem;              // [Hn][HP]  (h transposed: hs[hcol][row])
    float* xs = hs + Hn * HP;      // [TB][XP]
    float* ws = xs + TB * XP;      // [KB][128]
    int* ridx = (int*)(ws + KB * 128);  // [TB]
    int* act = ridx + TB;               // [TB]

    int tid = threadIdx.x;
    int tx = tid & 15;   // 16 col-groups of 8
    int ty = tid >> 4;   // 16 row-groups of 8

    if (tid < TB) {
        int r = r0 + tid;
        int idx = (r < cnt) ? g_alist[e * Bn + r] : -1;
        ridx[tid] = idx;
        act[tid] = (idx >= 0) ? actions[idx] : 0;
    }
    __syncthreads();

    const float* W1e = W1 + (size_t)e * Fn * Hn;
    const float* W2e = W2 + (size_t)e * Hn * An;

    float acc[8][8];
#pragma unroll
    for (int i = 0; i < 8; i++)
#pragma unroll
        for (int j = 0; j < 8; j++) acc[i][j] = 0.f;

    // ---- GEMM1: [128 x 512] * [512 x 128] ----
    for (int kc = 0; kc < Fn / KB; kc++) {
#pragma unroll
        for (int p = 0; p < 4; p++) {
            int r = p * 32 + (tid >> 3);
            int kk = (tid & 7) * 4;
            int row = ridx[r];
            if (row < 0) row = 0;
            float4 v = *(const float4*)(x + (size_t)row * Fn + kc * KB + kk);
            float* d = xs + r * XP + kk;
            d[0] = v.x; d[1] = v.y; d[2] = v.z; d[3] = v.w;
        }
#pragma unroll
        for (int p = 0; p < 4; p++) {
            int k = p * 8 + (tid >> 5);
            int h4 = (tid & 31) * 4;
            float4 v = *(const float4*)(W1e + (size_t)(kc * KB + k) * Hn + h4);
            *(float4*)(ws + k * Hn + h4) = v;
        }
        __syncthreads();
#pragma unroll 4
        for (int k = 0; k < KB; k++) {
            float a[8], bb[8];
#pragma unroll
            for (int i = 0; i < 8; i++) a[i] = xs[(ty * 8 + i) * XP + k];
            float4 bA = *(float4*)(ws + k * Hn + tx * 8);
            float4 bB = *(float4*)(ws + k * Hn + tx * 8 + 4);
            bb[0] = bA.x; bb[1] = bA.y; bb[2] = bA.z; bb[3] = bA.w;
            bb[4] = bB.x; bb[5] = bB.y; bb[6] = bB.z; bb[7] = bB.w;
#pragma unroll
            for (int i = 0; i < 8; i++)
#pragma unroll
                for (int j = 0; j < 8; j++) acc[i][j] += a[i] * bb[j];
        }
        __syncthreads();
    }

    // epilogue GEMM1: relu(+b1) -> hs transposed
#pragma unroll
    for (int j = 0; j < 8; j++) {
        int col = tx * 8 + j;
        float bv = b1[e * Hn + col];
#pragma unroll
        for (int i = 0; i < 8; i++) {
            float h = acc[i][j] + bv;
            hs[col * HP + ty * 8 + i] = h > 0.f ? h : 0.f;
        }
    }
    __syncthreads();

    // running softmax stats per row (8 rows per thread)
    float mrun[8], zrun[8], s1run[8], schrun[8];
#pragma unroll
    for (int i = 0; i < 8; i++) {
        mrun[i] = -1e30f; zrun[i] = 0.f; s1run[i] = 0.f; schrun[i] = -1e30f;
    }

    // ---- GEMM2 in two 128-col halves ----
    for (int ah = 0; ah < 2; ah++) {
        float acc2[8][8];
#pragma unroll
        for (int i = 0; i < 8; i++)
#pragma unroll
            for (int j = 0; j < 8; j++) acc2[i][j] = 0.f;

        for (int kc = 0; kc < Hn / KB; kc++) {
#pragma unroll
            for (int p = 0; p < 4; p++) {
                int k = p * 8 + (tid >> 5);
                int h4 = (tid & 31) * 4;
                float4 v = *(const float4*)(W2e + (size_t)(kc * KB + k) * An +
                                            ah * 128 + h4);
                *(float4*)(ws + k * 128 + h4) = v;
            }
            __syncthreads();
#pragma unroll 4
            for (int k = 0; k < KB; k++) {
                float a[8], bb[8];
#pragma unroll
                for (int i = 0; i < 8; i++)
                    a[i] = hs[(kc * KB + k) * HP + ty * 8 + i];
                float4 bA = *(float4*)(ws + k * 128 + tx * 8);
                float4 bB = *(float4*)(ws + k * 128 + tx * 8 + 4);
                bb[0] = bA.x; bb[1] = bA.y; bb[2] = bA.z; bb[3] = bA.w;
                bb[4] = bB.x; bb[5] = bB.y; bb[6] = bB.z; bb[7] = bB.w;
#pragma unroll
                for (int i = 0; i < 8; i++)
#pragma unroll
                    for (int j = 0; j < 8; j++) acc2[i][j] += a[i] * bb[j];
            }
            __syncthreads();
        }

        // softmax stats for this half, reduced over the 16 tx lanes
#pragma unroll
        for (int i = 0; i < 8; i++) {
            float s[8];
#pragma unroll
            for (int j = 0; j < 8; j++)
                s[j] = acc2[i][j] + b2[e * An + ah * 128 + tx * 8 + j];
            float mx = s[0];
#pragma unroll
            for (int j = 1; j < 8; j++) mx = fmaxf(mx, s[j]);
#pragma unroll
            for (int off = 1; off <= 8; off <<= 1)
                mx = fmaxf(mx, __shfl_xor_sync(0xffffffffu, mx, off));
            float z = 0.f, s1v = 0.f;
#pragma unroll
            for (int j = 0; j < 8; j++) {
                float p = __expf(s[j] - mx);
                z += p;
                s1v += s[j] * p;
            }
            int arow = act[ty * 8 + i];
            int cb = ah * 128 + tx * 8;
            float sc = -1e30f;
            if (arow >= cb && arow < cb + 8) sc = s[arow - cb];
#pragma unroll
            for (int off = 1; off <= 8; off <<= 1) {
                z += __shfl_xor_sync(0xffffffffu, z, off);
                s1v += __shfl_xor_sync(0xffffffffu, s1v, off);
                sc = fmaxf(sc, __shfl_xor_sync(0xffffffffu, sc, off));
            }
            // merge half into running stats
            float M = fmaxf(mrun[i], mx);
            float e1 = __expf(mrun[i] - M);
            float e2 = __expf(mx - M);
            zrun[i] = zrun[i] * e1 + z * e2;
            s1run[i] = s1run[i] * e1 + s1v * e2;
            mrun[i] = M;
            schrun[i] = fmaxf(schrun[i], sc);
        }
    }

    if (tx == 0) {
#pragma unroll
        for (int i = 0; i < 8; i++) {
            int r = ty * 8 + i;
            if (r0 + r < cnt) {
                int b = ridx[r];
                float lz = mrun[i] + __logf(zrun[i]);
                out[(size_t)b * 3 + 0] = schrun[i] - lz;
                out[(size_t)b * 3 + 2] = s1run[i] / zrun[i] - lz;
            }
        }
    }
}

// ---------------------------------------------------------------------------
// Critic: per (task, 128-row tile): hc = relu(X*W1+b1) [128x32],
// v = hc . W2 + b2. Writes out[:,1].
// ---------------------------------------------------------------------------
extern "C" __global__ void __launch_bounds__(256)
critic_kernel(const float* __restrict__ x, const float* __restrict__ W1,
              const float* __restrict__ b1c, const float* __restrict__ W2,
              const float* __restrict__ b2c, float* __restrict__ out) {
    int t = blockIdx.y;
    int cnt = g_ccnt[t];
    int r0 = blockIdx.x * TB;
    if (r0 >= cnt) return;

    __shared__ float xs[TB * XP];
    __shared__ float wc[KB * HCn];
    __shared__ int ridx[TB];

    int tid = threadIdx.x;
    int tx = tid & 7;   // 8 col-groups of 4
    int ty = tid >> 3;  // 32 row-groups of 4

    if (tid < TB) {
        int r = r0 + tid;
        ridx[tid] = (r < cnt) ? g_clist[t * Bn + r] : -1;
    }
    __syncthreads();

    const float* W1t = W1 + (size_t)t * Fn * HCn;

    float acc[4][4];
#pragma unroll
    for (int i = 0; i < 4; i++)
#pragma unroll
        for (int j = 0; j < 4; j++) acc[i][j] = 0.f;

    for (int kc = 0; kc < Fn / KB; kc++) {
#pragma unroll
        for (int p = 0; p < 4; p++) {
            int r = p * 32 + (tid >> 3);
            int kk = (tid & 7) * 4;
            int row = ridx[r];
            if (row < 0) row = 0;
            float4 v = *(const float4*)(x + (size_t)row * Fn + kc * KB + kk);
            float* d = xs + r * XP + kk;
            d[0] = v.x; d[1] = v.y; d[2] = v.z; d[3] = v.w;
        }
        {
            int k = tid >> 3;
            int c4 = (tid & 7) * 4;
            float4 v = *(const float4*)(W1t + (size_t)(kc * KB + k) * HCn + c4);
            *(float4*)(wc + k * HCn + c4) = v;
        }
        __syncthreads();
#pragma unroll 8
        for (int k = 0; k < KB; k++) {
            float a[4];
#pragma unroll
            for (int i = 0; i < 4; i++) a[i] = xs[(ty * 4 + i) * XP + k];
            float4 bv = *(float4*)(wc + k * HCn + tx * 4);
#pragma unroll
            for (int i = 0; i < 4; i++) {
                acc[i][0] += a[i] * bv.x;
                acc[i][1] += a[i] * bv.y;
                acc[i][2] += a[i] * bv.z;
                acc[i][3] += a[i] * bv.w;
            }
        }
        __syncthreads();
    }

    float b1v[4], w2v[4];
#pragma unroll
    for (int j = 0; j < 4; j++) {
        b1v[j] = b1c[t * HCn + tx * 4 + j];
        w2v[j] = W2[t * HCn + tx * 4 + j];
    }
    float b2v = b2c[t];

#pragma unroll
    for (int i = 0; i < 4; i++) {
        float part = 0.f;
#pragma unroll
        for (int j = 0; j < 4; j++) {
            float h = acc[i][j] + b1v[j];
            h = h > 0.f ? h : 0.f;
            part += h * w2v[j];
        }
        part += __shfl_xor_sync(0xffffffffu, part, 1);
        part += __shfl_xor_sync(0xffffffffu, part, 2);
        part += __shfl_xor_sync(0xffffffffu, part, 4);
        int r = ty * 4 + i;
        if (tx == 0 && r0 + r < cnt) {
            int b = ridx[r];
            out[(size_t)b * 3 + 1] = part + b2v;
        }
    }
}

extern "C" void kernel_launch(void* const* d_in, const int* in_sizes, int n_in,
                              void* d_out, int out_size) {
    const float* x = (const float*)d_in[0];
    const int* commands = (const int*)d_in[1];
    const int* tasks = (const int*)d_in[2];
    const int* actions = (const int*)d_in[3];
    const float* A_W1 = (const float*)d_in[4];
    const float* A_b1 = (const float*)d_in[5];
    const float* A_W2 = (const float*)d_in[6];
    const float* A_b2 = (const float*)d_in[7];
    const float* C_W1 = (const float*)d_in[8];
    const float* C_b1 = (const float*)d_in[9];
    const float* C_W2 = (const float*)d_in[10];
    const float* C_b2 = (const float*)d_in[11];
    float* out = (float*)d_out;

    const int SMEM_A = (Hn * HP + TB * XP + KB * 128) * 4 + TB * 4 * 2;
    cudaFuncSetAttribute(actor_kernel,
                         cudaFuncAttributeMaxDynamicSharedMemorySize, SMEM_A);

    zero_kernel<<<1, 32>>>();
    route_kernel<<<Bn / 256, 256>>>(commands, tasks);
    actor_kernel<<<dim3((Bn + TB - 1) / TB, En), 256, SMEM_A>>>(
        x, actions, A_W1, A_b1, A_W2, A_b2, out);
    critic_kernel<<<dim3((Bn + TB - 1) / TB, Tn), 256>>>(
        x, C_W1, C_b1, C_W2, C_b2, out);
}

// round 5
// speedup vs baseline: 1.8523x; 1.8523x over previous
#include <cuda_runtime.h>
#include <cuda_bf16.h>
#include <mma.h>
#include <cstdint>

using namespace nvcuda;

#define Bn 32768
#define Fn 512
#define En 8
#define Hn 128
#define An 256
#define Tn 8
#define HCn 32
#define MT 64   // rows per tile
#define NTILES_MAX 520

// ---- smem layout (bytes, all 16B-aligned) ----
#define HF32  0          // [64][132] f32 staging (33792 B); xs nested inside
#define XS_HI 0          // [64][40] bf16 (5120)
#define XS_LO 5120       // [64][40] bf16 (5120)
#define HC32  12288      // critic [64][36] f32 (9216), inside HF32 region
#define HH    33792      // [64][136] bf16 (17408)
#define HL    51200      // [64][136] bf16 (17408)
#define BT_HI 68608      // [32][136] bf16 (8704)
#define BT_LO 77312      // [32][136] bf16 (8704)
#define RIDX  86016      // int[64]
#define ACTS  86272      // int[64]
#define AB1   86528      // float[128]
#define AB2   87040      // float[256]
#define CB1   88064      // float[32]
#define CW2S  88192      // float[32]
#define SMEM_TOTAL 88320

// ---- device scratch (allocation-free) ----
__device__ int g_acnt[En];
__device__ int g_ccnt[Tn];
__device__ int g_alist[En * Bn];
__device__ int g_clist[Tn * Bn];
__device__ __nv_bfloat16 g_aw1h[En * Fn * Hn];
__device__ __nv_bfloat16 g_aw1l[En * Fn * Hn];
__device__ __nv_bfloat16 g_aw2h[En * Hn * An];
__device__ __nv_bfloat16 g_aw2l[En * Hn * An];
__device__ __nv_bfloat16 g_cw1h[Tn * Fn * HCn];
__device__ __nv_bfloat16 g_cw1l[Tn * Fn * HCn];

typedef wmma::fragment<wmma::matrix_a, 16, 16, 16, __nv_bfloat16, wmma::row_major> FragA;
typedef wmma::fragment<wmma::matrix_b, 16, 16, 16, __nv_bfloat16, wmma::row_major> FragB;
typedef wmma::fragment<wmma::accumulator, 16, 16, 16, float> FragC;

// ---------------- routing ----------------
__global__ void zero_kernel() {
    int t = threadIdx.x;
    if (t < En) g_acnt[t] = 0;
    if (t < Tn) g_ccnt[t] = 0;
}

__global__ void route_kernel(const int* __restrict__ commands,
                             const int* __restrict__ tasks) {
    __shared__ int scA[En], scC[Tn], baseA[En], baseC[Tn];
    int tid = threadIdx.x;
    if (tid < En) scA[tid] = 0;
    if (tid < Tn) scC[tid] = 0;
    __syncthreads();
    int b = blockIdx.x * blockDim.x + tid;
    int e = commands[b];
    int pa = atomicAdd(&scA[e], 1);
    int t = tasks[b];
    int pc = atomicAdd(&scC[t], 1);
    __syncthreads();
    if (tid < En) baseA[tid] = atomicAdd(&g_acnt[tid], scA[tid]);
    if (tid < Tn) baseC[tid] = atomicAdd(&g_ccnt[tid], scC[tid]);
    __syncthreads();
    g_alist[e * Bn + baseA[e] + pa] = b;
    g_clist[t * Bn + baseC[t] + pc] = b;
}

// ---------------- weight split prep (elementwise, layouts already [k][n]) ----
__global__ void prep_kernel(const float* __restrict__ AW1, const float* __restrict__ AW2,
                            const float* __restrict__ CW1) {
    int i = blockIdx.x * 256 + threadIdx.x;
    if (i < En * Fn * Hn) {
        float f = AW1[i];
        __nv_bfloat16 h = __float2bfloat16(f);
        g_aw1h[i] = h;
        g_aw1l[i] = __float2bfloat16(f - __bfloat162float(h));
    } else if (i < En * Fn * Hn + En * Hn * An) {
        int j = i - En * Fn * Hn;
        float f = AW2[j];
        __nv_bfloat16 h = __float2bfloat16(f);
        g_aw2h[j] = h;
        g_aw2l[j] = __float2bfloat16(f - __bfloat162float(h));
    } else if (i < En * Fn * Hn + En * Hn * An + Tn * Fn * HCn) {
        int j = i - En * Fn * Hn - En * Hn * An;
        float f = CW1[j];
        __nv_bfloat16 h = __float2bfloat16(f);
        g_cw1h[j] = h;
        g_cw1l[j] = __float2bfloat16(f - __bfloat162float(h));
    }
}

__device__ __forceinline__ uint32_t pk(float a, float b) {
    __nv_bfloat162 t = __floats2bfloat162_rn(a, b);
    return *reinterpret_cast<uint32_t*>(&t);
}

// gather 16 fp32 of row chunk, split to bf16 hi/lo, store to xs tiles
__device__ __forceinline__ void gather16(unsigned char* sm, const float* __restrict__ x,
                                         int grow, int kc, int tid) {
    const float4* s = (const float4*)(x + (size_t)grow * Fn + kc * 32 + (tid & 1) * 16);
    float f[16];
    float4 v;
    v = s[0]; f[0] = v.x; f[1] = v.y; f[2] = v.z; f[3] = v.w;
    v = s[1]; f[4] = v.x; f[5] = v.y; f[6] = v.z; f[7] = v.w;
    v = s[2]; f[8] = v.x; f[9] = v.y; f[10] = v.z; f[11] = v.w;
    v = s[3]; f[12] = v.x; f[13] = v.y; f[14] = v.z; f[15] = v.w;
    float fh[16], fl[16];
#pragma unroll
    for (int i = 0; i < 16; i++) {
        float h = __bfloat162float(__float2bfloat16(f[i]));
        fh[i] = h;
        fl[i] = f[i] - h;
    }
    uint32_t base = (uint32_t)((tid >> 1) * 80 + (tid & 1) * 32);
    uint4* dh = (uint4*)(sm + XS_HI + base);
    uint4* dl = (uint4*)(sm + XS_LO + base);
    dh[0] = make_uint4(pk(fh[0], fh[1]), pk(fh[2], fh[3]), pk(fh[4], fh[5]), pk(fh[6], fh[7]));
    dh[1] = make_uint4(pk(fh[8], fh[9]), pk(fh[10], fh[11]), pk(fh[12], fh[13]), pk(fh[14], fh[15]));
    dl[0] = make_uint4(pk(fl[0], fl[1]), pk(fl[2], fl[3]), pk(fl[4], fl[5]), pk(fl[6], fl[7]));
    dl[1] = make_uint4(pk(fl[8], fl[9]), pk(fl[10], fl[11]), pk(fl[12], fl[13]), pk(fl[14], fl[15]));
}

// ---------------- fused actor + critic ----------------
extern "C" __global__ void __launch_bounds__(128)
fused_kernel(const float* __restrict__ x, const int* __restrict__ actions,
             const float* __restrict__ Ab1, const float* __restrict__ Ab2,
             const float* __restrict__ Cb1, const float* __restrict__ CW2,
             const float* __restrict__ Cb2, float* __restrict__ out) {
    extern __shared__ unsigned char sm[];
    int tid = threadIdx.x;
    int wid = tid >> 5;
    int wm = wid >> 1;   // warp row group (32 rows)
    int wn = wid & 1;    // warp col group
    bool is_actor = (blockIdx.z == 0);

    // prefix-scan tile scheduling (no dead blocks beyond rounding)
    int grp = -1, local = blockIdx.x;
    const int* cnts = is_actor ? g_acnt : g_ccnt;
#pragma unroll
    for (int i = 0; i < En; i++) {
        int nt = (cnts[i] + MT - 1) / MT;
        if (grp < 0) {
            if (local < nt) grp = i;
            else local -= nt;
        }
    }
    if (grp < 0) return;
    int cnt = cnts[grp];
    int r0 = local * MT;

    int* ridx = (int*)(sm + RIDX);
    int* acts = (int*)(sm + ACTS);
    if (tid < MT) {
        int r = r0 + tid;
        const int* list = is_actor ? (g_alist + grp * Bn) : (g_clist + grp * Bn);
        int idx = (r < cnt) ? list[r] : -1;
        ridx[tid] = idx;
        if (is_actor) acts[tid] = (idx >= 0) ? actions[idx] : 0;
    }
    if (is_actor) {
        ((float*)(sm + AB1))[tid] = Ab1[grp * Hn + tid];
        ((float*)(sm + AB2))[tid] = Ab2[grp * An + tid];
        ((float*)(sm + AB2))[128 + tid] = Ab2[grp * An + 128 + tid];
    } else if (tid < HCn) {
        ((float*)(sm + CB1))[tid] = Cb1[grp * HCn + tid];
        ((float*)(sm + CW2S))[tid] = CW2[grp * HCn + tid];
    }
    __syncthreads();
    int rr = ridx[tid >> 1];
    int grow = rr < 0 ? 0 : rr;

    if (is_actor) {
        // ======== GEMM1: h = x @ W1  [64 x 512 x 128] ========
        FragC acc[2][4];
#pragma unroll
        for (int mi = 0; mi < 2; mi++)
#pragma unroll
            for (int ni = 0; ni < 4; ni++) wmma::fill_fragment(acc[mi][ni], 0.f);

        for (int kc = 0; kc < 16; kc++) {
            gather16(sm, x, grow, kc, tid);
            {   // W1 tile [32 k][128 n] hi/lo
                int k = tid >> 2, nq = tid & 3;
                const uint4* gh = (const uint4*)(g_aw1h +
                    (((size_t)grp * Fn + kc * 32 + k) << 7) + nq * 32);
                const uint4* gl = (const uint4*)(g_aw1l +
                    (((size_t)grp * Fn + kc * 32 + k) << 7) + nq * 32);
                uint4* dh = (uint4*)(sm + BT_HI + k * 272 + nq * 64);
                uint4* dl = (uint4*)(sm + BT_LO + k * 272 + nq * 64);
#pragma unroll
                for (int q = 0; q < 4; q++) { dh[q] = gh[q]; dl[q] = gl[q]; }
            }
            __syncthreads();
#pragma unroll
            for (int ks = 0; ks < 2; ks++) {
                FragA ah[2], al[2];
#pragma unroll
                for (int mi = 0; mi < 2; mi++) {
                    const __nv_bfloat16* ap = (const __nv_bfloat16*)(sm + XS_HI) +
                        (wm * 32 + mi * 16) * 40 + ks * 16;
                    wmma::load_matrix_sync(ah[mi], ap, 40);
                    wmma::load_matrix_sync(al[mi],
                        (const __nv_bfloat16*)(sm + XS_LO) + (wm * 32 + mi * 16) * 40 + ks * 16, 40);
                }
#pragma unroll
                for (int ni = 0; ni < 4; ni++) {
                    FragB bh, bl;
                    wmma::load_matrix_sync(bh, (const __nv_bfloat16*)(sm + BT_HI) +
                        ks * 16 * 136 + wn * 64 + ni * 16, 136);
                    wmma::load_matrix_sync(bl, (const __nv_bfloat16*)(sm + BT_LO) +
                        ks * 16 * 136 + wn * 64 + ni * 16, 136);
#pragma unroll
                    for (int mi = 0; mi < 2; mi++) {
                        wmma::mma_sync(acc[mi][ni], ah[mi], bh, acc[mi][ni]);
                        wmma::mma_sync(acc[mi][ni], ah[mi], bl, acc[mi][ni]);
                        wmma::mma_sync(acc[mi][ni], al[mi], bh, acc[mi][ni]);
                    }
                }
            }
            __syncthreads();
        }
        // epilogue 1: stage f32, relu+bias, split to bf16 hi/lo
#pragma unroll
        for (int mi = 0; mi < 2; mi++)
#pragma unroll
            for (int ni = 0; ni < 4; ni++)
                wmma::store_matrix_sync((float*)(sm + HF32) +
                    (wm * 32 + mi * 16) * 132 + wn * 64 + ni * 16,
                    acc[mi][ni], 132, wmma::mem_row_major);
        __syncthreads();
        {
            int row = tid >> 1, c0 = (tid & 1) * 64;
            const float* hp = (const float*)(sm + HF32) + row * 132 + c0;
            const float* bp = (const float*)(sm + AB1) + c0;
            uint4* hhp = (uint4*)(sm + HH + (row * 136 + c0) * 2);
            uint4* hlp = (uint4*)(sm + HL + (row * 136 + c0) * 2);
#pragma unroll
            for (int g = 0; g < 8; g++) {
                float fh[8], fl[8];
#pragma unroll
                for (int i = 0; i < 8; i++) {
                    float h = hp[g * 8 + i] + bp[g * 8 + i];
                    h = h > 0.f ? h : 0.f;
                    float hh = __bfloat162float(__float2bfloat16(h));
                    fh[i] = hh;
                    fl[i] = h - hh;
                }
                hhp[g] = make_uint4(pk(fh[0], fh[1]), pk(fh[2], fh[3]),
                                    pk(fh[4], fh[5]), pk(fh[6], fh[7]));
                hlp[g] = make_uint4(pk(fl[0], fl[1]), pk(fl[2], fl[3]),
                                    pk(fl[4], fl[5]), pk(fl[6], fl[7]));
            }
        }
        __syncthreads();

        // ======== GEMM2: scores = h @ W2, two N=128 halves, online softmax ===
        float mrun = -3e38f, zrun = 0.f, s1run = 0.f, schrun = -3e38f;
        int myact = acts[tid >> 1];
#pragma unroll 1
        for (int half = 0; half < 2; half++) {
            FragC a2[2][4];
#pragma unroll
            for (int mi = 0; mi < 2; mi++)
#pragma unroll
                for (int ni = 0; ni < 4; ni++) wmma::fill_fragment(a2[mi][ni], 0.f);
#pragma unroll 1
            for (int kc = 0; kc < 4; kc++) {
                {   // W2 tile [32 k][128 n] from half
                    int k = tid >> 2, nq = tid & 3;
                    size_t gb = ((size_t)grp * Hn + kc * 32 + k) * An + half * 128 + nq * 32;
                    const uint4* gh = (const uint4*)(g_aw2h + gb);
                    const uint4* gl = (const uint4*)(g_aw2l + gb);
                    uint4* dh = (uint4*)(sm + BT_HI + k * 272 + nq * 64);
                    uint4* dl = (uint4*)(sm + BT_LO + k * 272 + nq * 64);
#pragma unroll
                    for (int q = 0; q < 4; q++) { dh[q] = gh[q]; dl[q] = gl[q]; }
                }
                __syncthreads();
#pragma unroll
                for (int ks = 0; ks < 2; ks++) {
                    FragA ah[2], al[2];
#pragma unroll
                    for (int mi = 0; mi < 2; mi++) {
                        wmma::load_matrix_sync(ah[mi], (const __nv_bfloat16*)(sm + HH) +
                            (wm * 32 + mi * 16) * 136 + kc * 32 + ks * 16, 136);
                        wmma::load_matrix_sync(al[mi], (const __nv_bfloat16*)(sm + HL) +
                            (wm * 32 + mi * 16) * 136 + kc * 32 + ks * 16, 136);
                    }
#pragma unroll
                    for (int ni = 0; ni < 4; ni++) {
                        FragB bh, bl;
                        wmma::load_matrix_sync(bh, (const __nv_bfloat16*)(sm + BT_HI) +
                            ks * 16 * 136 + wn * 64 + ni * 16, 136);
                        wmma::load_matrix_sync(bl, (const __nv_bfloat16*)(sm + BT_LO) +
                            ks * 16 * 136 + wn * 64 + ni * 16, 136);
#pragma unroll
                        for (int mi = 0; mi < 2; mi++) {
                            wmma::mma_sync(a2[mi][ni], ah[mi], bh, a2[mi][ni]);
                            wmma::mma_sync(a2[mi][ni], ah[mi], bl, a2[mi][ni]);
                            wmma::mma_sync(a2[mi][ni], al[mi], bh, a2[mi][ni]);
                        }
                    }
                }
                __syncthreads();
            }
#pragma unroll
            for (int mi = 0; mi < 2; mi++)
#pragma unroll
                for (int ni = 0; ni < 4; ni++)
                    wmma::store_matrix_sync((float*)(sm + HF32) +
                        (wm * 32 + mi * 16) * 132 + wn * 64 + ni * 16,
                        a2[mi][ni], 132, wmma::mem_row_major);
            __syncthreads();
            // softmax partial: lane pair (2r, 2r+1) splits row r's 128 cols
            {
                int row = tid >> 1, c0 = (tid & 1) * 64;
                const float* sp = (const float*)(sm + HF32) + row * 132 + c0;
                const float* bp = (const float*)(sm + AB2) + half * 128 + c0;
                float mx = -3e38f;
#pragma unroll 8
                for (int c = 0; c < 64; c++) mx = fmaxf(mx, sp[c] + bp[c]);
                float z = 0.f, s1 = 0.f, sch = -3e38f;
                int abase = half * 128 + c0;
#pragma unroll 8
                for (int c = 0; c < 64; c++) {
                    float s = sp[c] + bp[c];
                    float p = __expf(s - mx);
                    z += p;
                    s1 += s * p;
                    if (abase + c == myact) sch = s;
                }
                // pair merge
                float mo = __shfl_xor_sync(0xffffffffu, mx, 1);
                float zo = __shfl_xor_sync(0xffffffffu, z, 1);
                float so = __shfl_xor_sync(0xffffffffu, s1, 1);
                float co = __shfl_xor_sync(0xffffffffu, sch, 1);
                float M = fmaxf(mx, mo);
                float f1 = __expf(mx - M), f2 = __expf(mo - M);
                z = z * f1 + zo * f2;
                s1 = s1 * f1 + so * f2;
                sch = fmaxf(sch, co);
                // merge into running
                float MM = fmaxf(mrun, M);
                float g1 = __expf(mrun - MM), g2 = __expf(M - MM);
                zrun = zrun * g1 + z * g2;
                s1run = s1run * g1 + s1 * g2;
                mrun = MM;
                schrun = fmaxf(schrun, sch);
            }
            __syncthreads();
        }
        {
            int row = tid >> 1;
            if ((tid & 1) == 0 && r0 + row < cnt) {
                int b = ridx[row];
                float lz = mrun + __logf(zrun);
                out[(size_t)b * 3 + 0] = schrun - lz;
                out[(size_t)b * 3 + 2] = s1run / zrun - lz;
            }
        }
    } else {
        // ======== Critic: v = relu(x@W1+b1) . W2 + b2  [64 x 512 x 32] ========
        FragC acc[2];
        wmma::fill_fragment(acc[0], 0.f);
        wmma::fill_fragment(acc[1], 0.f);
        for (int kc = 0; kc < 16; kc++) {
            gather16(sm, x, grow, kc, tid);
            {   // CW1 tile [32 k][32 n]
                int k = tid >> 2, nq = tid & 3;
                size_t gb = ((size_t)grp * Fn + kc * 32 + k) * HCn + nq * 8;
                *(uint4*)(sm + BT_HI + k * 80 + nq * 16) = *(const uint4*)(g_cw1h + gb);
                *(uint4*)(sm + BT_LO + k * 80 + nq * 16) = *(const uint4*)(g_cw1l + gb);
            }
            __syncthreads();
#pragma unroll
            for (int ks = 0; ks < 2; ks++) {
                FragA ah[2], al[2];
#pragma unroll
                for (int mi = 0; mi < 2; mi++) {
                    wmma::load_matrix_sync(ah[mi], (const __nv_bfloat16*)(sm + XS_HI) +
                        (wm * 32 + mi * 16) * 40 + ks * 16, 40);
                    wmma::load_matrix_sync(al[mi], (const __nv_bfloat16*)(sm + XS_LO) +
                        (wm * 32 + mi * 16) * 40 + ks * 16, 40);
                }
                FragB bh, bl;
                wmma::load_matrix_sync(bh, (const __nv_bfloat16*)(sm + BT_HI) +
                    ks * 16 * 40 + wn * 16, 40);
                wmma::load_matrix_sync(bl, (const __nv_bfloat16*)(sm + BT_LO) +
                    ks * 16 * 40 + wn * 16, 40);
#pragma unroll
                for (int mi = 0; mi < 2; mi++) {
                    wmma::mma_sync(acc[mi], ah[mi], bh, acc[mi]);
                    wmma::mma_sync(acc[mi], ah[mi], bl, acc[mi]);
                    wmma::mma_sync(acc[mi], al[mi], bh, acc[mi]);
                }
            }
            __syncthreads();
        }
#pragma unroll
        for (int mi = 0; mi < 2; mi++)
            wmma::store_matrix_sync((float*)(sm + HC32) + (wm * 32 + mi * 16) * 36 + wn * 16,
                                    acc[mi], 36, wmma::mem_row_major);
        __syncthreads();
        {
            int row = tid >> 1, c0 = (tid & 1) * 16;
            const float* hp = (const float*)(sm + HC32) + row * 36 + c0;
            const float* b1p = (const float*)(sm + CB1) + c0;
            const float* w2p = (const float*)(sm + CW2S) + c0;
            float sum = 0.f;
#pragma unroll
            for (int c = 0; c < 16; c++) {
                float h = hp[c] + b1p[c];
                h = h > 0.f ? h : 0.f;
                sum += h * w2p[c];
            }
            sum += __shfl_xor_sync(0xffffffffu, sum, 1);
            if ((tid & 1) == 0 && r0 + row < cnt)
                out[(size_t)ridx[row] * 3 + 1] = sum + Cb2[grp];
        }
    }
}

extern "C" void kernel_launch(void* const* d_in, const int* in_sizes, int n_in,
                              void* d_out, int out_size) {
    const float* x = (const float*)d_in[0];
    const int* commands = (const int*)d_in[1];
    const int* tasks = (const int*)d_in[2];
    const int* actions = (const int*)d_in[3];
    const float* A_W1 = (const float*)d_in[4];
    const float* A_b1 = (const float*)d_in[5];
    const float* A_W2 = (const float*)d_in[6];
    const float* A_b2 = (const float*)d_in[7];
    const float* C_W1 = (const float*)d_in[8];
    const float* C_b1 = (const float*)d_in[9];
    const float* C_W2 = (const float*)d_in[10];
    const float* C_b2 = (const float*)d_in[11];
    float* out = (float*)d_out;

    cudaFuncSetAttribute(fused_kernel, cudaFuncAttributeMaxDynamicSharedMemorySize,
                         SMEM_TOTAL);

    zero_kernel<<<1, 32>>>();
    route_kernel<<<Bn / 256, 256>>>(commands, tasks);
    int prep_elems = En * Fn * Hn + En * Hn * An + Tn * Fn * HCn;
    prep_kernel<<<(prep_elems + 255) / 256, 256>>>(A_W1, A_W2, C_W1);
    fused_kernel<<<dim3(NTILES_MAX, 1, 2), 128, SMEM_TOTAL>>>(
        x, actions, A_b1, A_b2, C_b1, C_W2, C_b2, out);
}

// round 8
// speedup vs baseline: 2.0811x; 1.1235x over previous
#include <cuda_runtime.h>
#include <cuda_bf16.h>
#include <mma.h>
#include <cstdint>

using namespace nvcuda;

#define Bn 32768
#define Fn 512
#define En 8
#define Hn 128
#define An 256
#define Tn 8
#define HCn 32
#define MT 64
#define NTILES_MAX 520

// ---- smem layout (bytes) ----
#define XS_HI 0          // [64][40] bf16 (5120)
#define XS_LO 5120       // [64][40] bf16 (5120)
#define BTA   10240      // weight tile buf A: hi [32][136] 8704 | lo 8704
#define BTB   27648      // weight tile buf B
#define HH    45056      // [64][136] bf16 (17408)
#define HL    62464      // [64][136] bf16 (17408)
#define RIDX  79872      // int[64]
#define ACTS  80128      // int[64]
#define AB1   80384      // float[128]
#define AB2   80896      // float[256]
#define CB1   81920      // float[32]
#define CW2S  82048      // float[32]
#define SMEM_TOTAL 82176

// ---- device scratch ----
__device__ int g_acnt[En];
__device__ int g_ccnt[Tn];
__device__ int g_alist[En * Bn];
__device__ int g_clist[Tn * Bn];
__device__ __nv_bfloat16 g_aw1h[En * Fn * Hn];
__device__ __nv_bfloat16 g_aw1l[En * Fn * Hn];
__device__ __nv_bfloat16 g_aw2h[En * Hn * An];
__device__ __nv_bfloat16 g_aw2l[En * Hn * An];
__device__ __nv_bfloat16 g_cw1h[Tn * Fn * HCn];
__device__ __nv_bfloat16 g_cw1l[Tn * Fn * HCn];

typedef wmma::fragment<wmma::matrix_a, 16, 16, 16, __nv_bfloat16, wmma::row_major> FragA;
typedef wmma::fragment<wmma::matrix_b, 16, 16, 16, __nv_bfloat16, wmma::row_major> FragB;
typedef wmma::fragment<wmma::accumulator, 16, 16, 16, float> FragC;

// ---------------- routing ----------------
__global__ void zero_kernel() {
    int t = threadIdx.x;
    if (t < En) g_acnt[t] = 0;
    if (t < Tn) g_ccnt[t] = 0;
}

__global__ void route_kernel(const int* __restrict__ commands,
                             const int* __restrict__ tasks) {
    __shared__ int scA[En], scC[Tn], baseA[En], baseC[Tn];
    int tid = threadIdx.x;
    if (tid < En) scA[tid] = 0;
    if (tid < Tn) scC[tid] = 0;
    __syncthreads();
    int b = blockIdx.x * blockDim.x + tid;
    int e = commands[b];
    int pa = atomicAdd(&scA[e], 1);
    int t = tasks[b];
    int pc = atomicAdd(&scC[t], 1);
    __syncthreads();
    if (tid < En) baseA[tid] = atomicAdd(&g_acnt[tid], scA[tid]);
    if (tid < Tn) baseC[tid] = atomicAdd(&g_ccnt[tid], scC[tid]);
    __syncthreads();
    g_alist[e * Bn + baseA[e] + pa] = b;
    g_clist[t * Bn + baseC[t] + pc] = b;
}

// ---------------- weight split prep ----------------
__global__ void prep_kernel(const float* __restrict__ AW1, const float* __restrict__ AW2,
                            const float* __restrict__ CW1) {
    int i = blockIdx.x * 256 + threadIdx.x;
    if (i < En * Fn * Hn) {
        float f = AW1[i];
        __nv_bfloat16 h = __float2bfloat16(f);
        g_aw1h[i] = h;
        g_aw1l[i] = __float2bfloat16(f - __bfloat162float(h));
    } else if (i < En * Fn * Hn + En * Hn * An) {
        int j = i - En * Fn * Hn;
        float f = AW2[j];
        __nv_bfloat16 h = __float2bfloat16(f);
        g_aw2h[j] = h;
        g_aw2l[j] = __float2bfloat16(f - __bfloat162float(h));
    } else if (i < En * Fn * Hn + En * Hn * An + Tn * Fn * HCn) {
        int j = i - En * Fn * Hn - En * Hn * An;
        float f = CW1[j];
        __nv_bfloat16 h = __float2bfloat16(f);
        g_cw1h[j] = h;
        g_cw1l[j] = __float2bfloat16(f - __bfloat162float(h));
    }
}

// ---------------- helpers ----------------
__device__ __forceinline__ uint32_t pk(float a, float b) {
    __nv_bfloat162 t = __floats2bfloat162_rn(a, b);
    return *reinterpret_cast<uint32_t*>(&t);
}

__device__ __forceinline__ void split8(const float* f, uint4& hi, uint4& lo) {
    float fh[8], fl[8];
#pragma unroll
    for (int i = 0; i < 8; i++) {
        float h = __bfloat162float(__float2bfloat16(f[i]));
        fh[i] = h;
        fl[i] = f[i] - h;
    }
    hi = make_uint4(pk(fh[0], fh[1]), pk(fh[2], fh[3]), pk(fh[4], fh[5]), pk(fh[6], fh[7]));
    lo = make_uint4(pk(fl[0], fl[1]), pk(fl[2], fl[3]), pk(fl[4], fl[5]), pk(fl[6], fl[7]));
}

__device__ __forceinline__ uint32_t s2u(const void* p) {
    return (uint32_t)__cvta_generic_to_shared(p);
}
__device__ __forceinline__ void cpa(uint32_t d, const void* s) {
    asm volatile("cp.async.cg.shared.global [%0], [%1], 16;" :: "r"(d), "l"(s));
}
#define CPC() asm volatile("cp.async.commit_group;")
#define CPW1() asm volatile("cp.async.wait_group 1;")
#define CPW0() asm volatile("cp.async.wait_group 0;")

// prefetch 32 fp32 (16 per lane-pair half) into regs
__device__ __forceinline__ void ldx(float* r, const float* __restrict__ x, int grow,
                                    int kc, int tid) {
    const float4* s = (const float4*)(x + (size_t)grow * Fn + kc * 32 + (tid & 1) * 16);
    float4 v;
    v = s[0]; r[0] = v.x; r[1] = v.y; r[2] = v.z; r[3] = v.w;
    v = s[1]; r[4] = v.x; r[5] = v.y; r[6] = v.z; r[7] = v.w;
    v = s[2]; r[8] = v.x; r[9] = v.y; r[10] = v.z; r[11] = v.w;
    v = s[3]; r[12] = v.x; r[13] = v.y; r[14] = v.z; r[15] = v.w;
}

// split prefetched regs, store into XS tiles
__device__ __forceinline__ void stx(unsigned char* sm, const float* r, int tid) {
    uint32_t base = (uint32_t)((tid >> 1) * 80 + (tid & 1) * 32);
    uint4 h0, l0, h1, l1;
    split8(r, h0, l0);
    split8(r + 8, h1, l1);
    uint4* dh = (uint4*)(sm + XS_HI + base);
    uint4* dl = (uint4*)(sm + XS_LO + base);
    dh[0] = h0; dh[1] = h1;
    dl[0] = l0; dl[1] = l1;
}

// cp.async issue: actor W1 tile kc -> buf (hi at +0, lo at +8704, stride 272B)
__device__ __forceinline__ void issue_w1(unsigned char* sm, int bt, int grp, int kc, int tid) {
    int k = tid >> 2, nq = tid & 3;
    size_t gb = (((size_t)grp * Fn + kc * 32 + k) << 7) + nq * 32;
    uint32_t dh = s2u(sm + bt) + k * 272 + nq * 64;
#pragma unroll
    for (int q = 0; q < 4; q++) {
        cpa(dh + q * 16, g_aw1h + gb + q * 8);
        cpa(dh + 8704 + q * 16, g_aw1l + gb + q * 8);
    }
}
// actor W2 tile, global k-group kcg (0..7): half=kcg>>2, kcl=kcg&3
__device__ __forceinline__ void issue_w2(unsigned char* sm, int bt, int grp, int kcg, int tid) {
    int half = kcg >> 2, kcl = kcg & 3;
    int k = tid >> 2, nq = tid & 3;
    size_t gb = ((size_t)grp * Hn + kcl * 32 + k) * An + half * 128 + nq * 32;
    uint32_t dh = s2u(sm + bt) + k * 272 + nq * 64;
#pragma unroll
    for (int q = 0; q < 4; q++) {
        cpa(dh + q * 16, g_aw2h + gb + q * 8);
        cpa(dh + 8704 + q * 16, g_aw2l + gb + q * 8);
    }
}
// critic W tile kc -> buf (hi at +0 stride 80B, lo at +8704)
__device__ __forceinline__ void issue_cw(unsigned char* sm, int bt, int grp, int kc, int tid) {
    int k = tid >> 2, nq = tid & 3;
    size_t gb = ((size_t)grp * Fn + kc * 32 + k) * HCn + nq * 8;
    uint32_t d = s2u(sm + bt) + k * 80 + nq * 16;
    cpa(d, g_cw1h + gb);
    cpa(d + 8704, g_cw1l + gb);
}

// ---------------- fused actor + critic ----------------
extern "C" __global__ void __launch_bounds__(128)
fused_kernel(const float* __restrict__ x, const int* __restrict__ actions,
             const float* __restrict__ Ab1, const float* __restrict__ Ab2,
             const float* __restrict__ Cb1, const float* __restrict__ CW2,
             const float* __restrict__ Cb2, float* __restrict__ out) {
    extern __shared__ unsigned char sm[];
    int tid = threadIdx.x;
    int wid = tid >> 5;
    int wm = wid >> 1;
    int wn = wid & 1;
    bool is_actor = (blockIdx.z == 0);

    int grp = -1, local = blockIdx.x;
    const int* cnts = is_actor ? g_acnt : g_ccnt;
#pragma unroll
    for (int i = 0; i < En; i++) {
        int nt = (cnts[i] + MT - 1) / MT;
        if (grp < 0) {
            if (local < nt) grp = i;
            else local -= nt;
        }
    }
    if (grp < 0) return;
    int cnt = cnts[grp];
    int r0 = local * MT;

    int* ridx = (int*)(sm + RIDX);
    int* acts = (int*)(sm + ACTS);
    if (tid < MT) {
        int r = r0 + tid;
        const int* list = is_actor ? (g_alist + grp * Bn) : (g_clist + grp * Bn);
        int idx = (r < cnt) ? list[r] : -1;
        ridx[tid] = idx;
        if (is_actor) acts[tid] = (idx >= 0) ? actions[idx] : 0;
    }
    if (is_actor) {
        ((float*)(sm + AB1))[tid] = Ab1[grp * Hn + tid];
        ((float*)(sm + AB2))[tid] = Ab2[grp * An + tid];
        ((float*)(sm + AB2))[128 + tid] = Ab2[grp * An + 128 + tid];
    } else if (tid < HCn) {
        ((float*)(sm + CB1))[tid] = Cb1[grp * HCn + tid];
        ((float*)(sm + CW2S))[tid] = CW2[grp * HCn + tid];
    }
    __syncthreads();
    int rr = ridx[tid >> 1];
    int grow = rr < 0 ? 0 : rr;
    float xr[16];

    if (is_actor) {
        // ======== GEMM1: h = x @ W1 [64 x 512 x 128], pipelined ========
        FragC acc[2][4];
#pragma unroll
        for (int mi = 0; mi < 2; mi++)
#pragma unroll
            for (int ni = 0; ni < 4; ni++) wmma::fill_fragment(acc[mi][ni], 0.f);

        issue_w1(sm, BTA, grp, 0, tid);
        CPC();
        ldx(xr, x, grow, 0, tid);

        for (int kc = 0; kc < 16; kc++) {
            int bt = (kc & 1) ? BTB : BTA;
            int other = (kc & 1) ? BTA : BTB;
            stx(sm, xr, tid);
            if (kc < 15) {
                issue_w1(sm, other, grp, kc + 1, tid);
                CPC();
                ldx(xr, x, grow, kc + 1, tid);
            } else {
                issue_w2(sm, other, grp, 0, tid);  // prefetch GEMM2 kcg0 -> BTA
                CPC();
            }
            CPW1();
            __syncthreads();
            const __nv_bfloat16* bh = (const __nv_bfloat16*)(sm + bt);
            const __nv_bfloat16* bl = (const __nv_bfloat16*)(sm + bt + 8704);
#pragma unroll
            for (int ks = 0; ks < 2; ks++) {
                FragA ah[2], al[2];
#pragma unroll
                for (int mi = 0; mi < 2; mi++) {
                    const __nv_bfloat16* ap = (const __nv_bfloat16*)(sm + XS_HI) +
                        (wm * 32 + mi * 16) * 40 + ks * 16;
                    wmma::load_matrix_sync(ah[mi], ap, 40);
                    wmma::load_matrix_sync(al[mi], (const __nv_bfloat16*)(sm + XS_LO) +
                        (wm * 32 + mi * 16) * 40 + ks * 16, 40);
                }
#pragma unroll
                for (int ni = 0; ni < 4; ni++) {
                    FragB fbh, fbl;
                    wmma::load_matrix_sync(fbh, bh + ks * 16 * 136 + wn * 64 + ni * 16, 136);
                    wmma::load_matrix_sync(fbl, bl + ks * 16 * 136 + wn * 64 + ni * 16, 136);
#pragma unroll
                    for (int mi = 0; mi < 2; mi++) {
                        wmma::mma_sync(acc[mi][ni], ah[mi], fbh, acc[mi][ni]);
                        wmma::mma_sync(acc[mi][ni], ah[mi], fbl, acc[mi][ni]);
                        wmma::mma_sync(acc[mi][ni], al[mi], fbh, acc[mi][ni]);
                    }
                }
            }
            __syncthreads();
        }

        // ---- GEMM1 epilogue: stage via BTB (dead), two 64-col passes ----
        {
            float* stg = (float*)(sm + BTB);
#pragma unroll 1
            for (int pass = 0; pass < 2; pass++) {
                if (wn == pass) {
#pragma unroll
                    for (int mi = 0; mi < 2; mi++)
#pragma unroll
                        for (int ni = 0; ni < 4; ni++)
                            wmma::store_matrix_sync(stg + (wm * 32 + mi * 16) * 68 + ni * 16,
                                                    acc[mi][ni], 68, wmma::mem_row_major);
                }
                __syncthreads();
                int row = tid >> 1, c0 = (tid & 1) * 32;
                int gcol = pass * 64 + c0;
                const float* bp = (float*)(sm + AB1) + gcol;
                const float4* sp = (const float4*)(stg + row * 68 + c0);
#pragma unroll
                for (int g = 0; g < 4; g++) {
                    float4 v0 = sp[g * 2], v1 = sp[g * 2 + 1];
                    float f[8] = {v0.x, v0.y, v0.z, v0.w, v1.x, v1.y, v1.z, v1.w};
#pragma unroll
                    for (int i = 0; i < 8; i++) {
                        float h = f[i] + bp[g * 8 + i];
                        f[i] = h > 0.f ? h : 0.f;
                    }
                    uint4 hi, lo;
                    split8(f, hi, lo);
                    *(uint4*)(sm + HH + (row * 136 + gcol + g * 8) * 2) = hi;
                    *(uint4*)(sm + HL + (row * 136 + gcol + g * 8) * 2) = lo;
                }
                __syncthreads();
            }
        }

        // ======== GEMM2: scores = h @ W2, pipelined, online softmax ========
        float mrun = -3e38f, zrun = 0.f, s1run = 0.f, schrun = -3e38f;
        int myact = acts[tid >> 1];
        FragC a2[2][4];
#pragma unroll 1
        for (int half = 0; half < 2; half++) {
#pragma unroll
            for (int mi = 0; mi < 2; mi++)
#pragma unroll
                for (int ni = 0; ni < 4; ni++) wmma::fill_fragment(a2[mi][ni], 0.f);
#pragma unroll 1
            for (int kcl = 0; kcl < 4; kcl++) {
                int kcg = half * 4 + kcl;
                int bt = (kcg & 1) ? BTB : BTA;
                int other = (kcg & 1) ? BTA : BTB;
                if (kcg < 7) {
                    issue_w2(sm, other, grp, kcg + 1, tid);
                    CPC();
                    CPW1();
                } else {
                    CPW0();
                }
                __syncthreads();
                const __nv_bfloat16* bh = (const __nv_bfloat16*)(sm + bt);
                const __nv_bfloat16* bl = (const __nv_bfloat16*)(sm + bt + 8704);
#pragma unroll
                for (int ks = 0; ks < 2; ks++) {
                    FragA ah[2], al[2];
#pragma unroll
                    for (int mi = 0; mi < 2; mi++) {
                        wmma::load_matrix_sync(ah[mi], (const __nv_bfloat16*)(sm + HH) +
                            (wm * 32 + mi * 16) * 136 + kcl * 32 + ks * 16, 136);
                        wmma::load_matrix_sync(al[mi], (const __nv_bfloat16*)(sm + HL) +
                            (wm * 32 + mi * 16) * 136 + kcl * 32 + ks * 16, 136);
                    }
#pragma unroll
                    for (int ni = 0; ni < 4; ni++) {
                        FragB fbh, fbl;
                        wmma::load_matrix_sync(fbh, bh + ks * 16 * 136 + wn * 64 + ni * 16, 136);
                        wmma::load_matrix_sync(fbl, bl + ks * 16 * 136 + wn * 64 + ni * 16, 136);
#pragma unroll
                        for (int mi = 0; mi < 2; mi++) {
                            wmma::mma_sync(a2[mi][ni], ah[mi], fbh, a2[mi][ni]);
                            wmma::mma_sync(a2[mi][ni], ah[mi], fbl, a2[mi][ni]);
                            wmma::mma_sync(a2[mi][ni], al[mi], fbh, a2[mi][ni]);
                        }
                    }
                }
                __syncthreads();
            }
            // score epilogue for this half, two 64-col passes via dead buffer
            float* stg = (float*)(sm + ((half == 0) ? BTB : BTA));
#pragma unroll 1
            for (int pass = 0; pass < 2; pass++) {
                if (wn == pass) {
#pragma unroll
                    for (int mi = 0; mi < 2; mi++)
#pragma unroll
                        for (int ni = 0; ni < 4; ni++)
                            wmma::store_matrix_sync(stg + (wm * 32 + mi * 16) * 68 + ni * 16,
                                                    a2[mi][ni], 68, wmma::mem_row_major);
                }
                __syncthreads();
                int row = tid >> 1, c0 = (tid & 1) * 32;
                int abase = half * 128 + pass * 64 + c0;
                const float4* sp = (const float4*)(stg + row * 68 + c0);
                const float4* bp = (const float4*)((float*)(sm + AB2) + abase);
                float s[32];
                float mx = -3e38f;
#pragma unroll
                for (int g = 0; g < 8; g++) {
                    float4 a = sp[g], b = bp[g];
                    s[g * 4 + 0] = a.x + b.x; s[g * 4 + 1] = a.y + b.y;
                    s[g * 4 + 2] = a.z + b.z; s[g * 4 + 3] = a.w + b.w;
                    mx = fmaxf(mx, fmaxf(fmaxf(s[g * 4], s[g * 4 + 1]),
                                         fmaxf(s[g * 4 + 2], s[g * 4 + 3])));
                }
                float z = 0.f, s1 = 0.f, sch = -3e38f;
#pragma unroll
                for (int c = 0; c < 32; c++) {
                    float p = __expf(s[c] - mx);
                    z += p;
                    s1 += s[c] * p;
                    if (abase + c == myact) sch = s[c];
                }
                float mo = __shfl_xor_sync(0xffffffffu, mx, 1);
                float zo = __shfl_xor_sync(0xffffffffu, z, 1);
                float so = __shfl_xor_sync(0xffffffffu, s1, 1);
                float co = __shfl_xor_sync(0xffffffffu, sch, 1);
                float M = fmaxf(mx, mo);
                float f1 = __expf(mx - M), f2 = __expf(mo - M);
                z = z * f1 + zo * f2;
                s1 = s1 * f1 + so * f2;
                sch = fmaxf(sch, co);
                float MM = fmaxf(mrun, M);
                float g1 = __expf(mrun - MM), g2 = __expf(M - MM);
                zrun = zrun * g1 + z * g2;
                s1run = s1run * g1 + s1 * g2;
                mrun = MM;
                schrun = fmaxf(schrun, sch);
                __syncthreads();
            }
        }
        {
            int row = tid >> 1;
            if ((tid & 1) == 0 && r0 + row < cnt) {
                int b = ridx[row];
                float lz = mrun + __logf(zrun);
                out[(size_t)b * 3 + 0] = schrun - lz;
                out[(size_t)b * 3 + 2] = s1run / zrun - lz;
            }
        }
    } else {
        // ======== Critic [64 x 512 x 32], pipelined ========
        FragC acc[2];
        wmma::fill_fragment(acc[0], 0.f);
        wmma::fill_fragment(acc[1], 0.f);
        issue_cw(sm, BTA, grp, 0, tid);
        CPC();
        ldx(xr, x, grow, 0, tid);
        for (int kc = 0; kc < 16; kc++) {
            int bt = (kc & 1) ? BTB : BTA;
            int other = (kc & 1) ? BTA : BTB;
            stx(sm, xr, tid);
            if (kc < 15) {
                issue_cw(sm, other, grp, kc + 1, tid);
                CPC();
                ldx(xr, x, grow, kc + 1, tid);
                CPW1();
            } else {
                CPW0();
            }
            __syncthreads();
            const __nv_bfloat16* bh = (const __nv_bfloat16*)(sm + bt);
            const __nv_bfloat16* bl = (const __nv_bfloat16*)(sm + bt + 8704);
#pragma unroll
            for (int ks = 0; ks < 2; ks++) {
                FragA ah[2], al[2];
#pragma unroll
                for (int mi = 0; mi < 2; mi++) {
                    wmma::load_matrix_sync(ah[mi], (const __nv_bfloat16*)(sm + XS_HI) +
                        (wm * 32 + mi * 16) * 40 + ks * 16, 40);
                    wmma::load_matrix_sync(al[mi], (const __nv_bfloat16*)(sm + XS_LO) +
                        (wm * 32 + mi * 16) * 40 + ks * 16, 40);
                }
                FragB fbh, fbl;
                wmma::load_matrix_sync(fbh, bh + ks * 16 * 40 + wn * 16, 40);
                wmma::load_matrix_sync(fbl, bl + ks * 16 * 40 + wn * 16, 40);
#pragma unroll
                for (int mi = 0; mi < 2; mi++) {
                    wmma::mma_sync(acc[mi], ah[mi], fbh, acc[mi]);
                    wmma::mma_sync(acc[mi], ah[mi], fbl, acc[mi]);
                    wmma::mma_sync(acc[mi], al[mi], fbh, acc[mi]);
                }
            }
            __syncthreads();
        }
        float* stg = (float*)(sm + BTA);
#pragma unroll
        for (int mi = 0; mi < 2; mi++)
            wmma::store_matrix_sync(stg + (wm * 32 + mi * 16) * 36 + wn * 16, acc[mi], 36,
                                    wmma::mem_row_major);
        __syncthreads();
        {
            int row = tid >> 1, c0 = (tid & 1) * 16;
            const float4* hp = (const float4*)(stg + row * 36 + c0);
            const float4* b1p = (const float4*)((float*)(sm + CB1) + c0);
            const float4* w2p = (const float4*)((float*)(sm + CW2S) + c0);
            float sum = 0.f;
#pragma unroll
            for (int g = 0; g < 4; g++) {
                float4 h4 = hp[g], b4 = b1p[g], w4 = w2p[g];
                float h;
                h = h4.x + b4.x; sum += (h > 0.f ? h : 0.f) * w4.x;
                h = h4.y + b4.y; sum += (h > 0.f ? h : 0.f) * w4.y;
                h = h4.z + b4.z; sum += (h > 0.f ? h : 0.f) * w4.z;
                h = h4.w + b4.w; sum += (h > 0.f ? h : 0.f) * w4.w;
            }
            sum += __shfl_xor_sync(0xffffffffu, sum, 1);
            if ((tid & 1) == 0 && r0 + row < cnt)
                out[(size_t)ridx[row] * 3 + 1] = sum + Cb2[grp];
        }
    }
}

extern "C" void kernel_launch(void* const* d_in, const int* in_sizes, int n_in,
                              void* d_out, int out_size) {
    const float* x = (const float*)d_in[0];
    const int* commands = (const int*)d_in[1];
    const int* tasks = (const int*)d_in[2];
    const int* actions = (const int*)d_in[3];
    const float* A_W1 = (const float*)d_in[4];
    const float* A_b1 = (const float*)d_in[5];
    const float* A_W2 = (const float*)d_in[6];
    const float* A_b2 = (const float*)d_in[7];
    const float* C_W1 = (const float*)d_in[8];
    const float* C_b1 = (const float*)d_in[9];
    const float* C_W2 = (const float*)d_in[10];
    const float* C_b2 = (const float*)d_in[11];
    float* out = (float*)d_out;

    cudaFuncSetAttribute(fused_kernel, cudaFuncAttributeMaxDynamicSharedMemorySize,
                         SMEM_TOTAL);

    zero_kernel<<<1, 32>>>();
    route_kernel<<<Bn / 256, 256>>>(commands, tasks);
    int prep_elems = En * Fn * Hn + En * Hn * An + Tn * Fn * HCn;
    prep_kernel<<<(prep_elems + 255) / 256, 256>>>(A_W1, A_W2, C_W1);
    fused_kernel<<<dim3(NTILES_MAX, 1, 2), 128, SMEM_TOTAL>>>(
        x, actions, A_b1, A_b2, C_b1, C_W2, C_b2, out);
}

// round 10
// speedup vs baseline: 2.2905x; 1.1006x over previous
#include <cuda_runtime.h>
#include <cuda_bf16.h>
#include <mma.h>
#include <cstdint>

using namespace nvcuda;

#define Bn 32768
#define Fn 512
#define En 8
#define Hn 128
#define An 256
#define Tn 8
#define HCn 32
#define MT 64
#define NTILES_MAX 520

// ---- smem layout (bytes) ----
// XS: 2 x 6144 (x tiles, [64][24] bf16 hi + lo per buffer); doubles as f32 staging [64][36]
#define XS0   0
#define BT0   12288     // weight tile buffers: 2 x 8704 ([16][136] bf16 hi at +0, lo at +4352)
#define HH    29696     // [64][136] bf16 (17408)
#define HL    47104     // [64][136] bf16 (17408)
#define RIDX  64512
#define ACTS  64768
#define AB1   65024
#define AB2   65536
#define CB1   66560
#define CW2S  66688
#define SMEM_TOTAL 66816

// ---- device scratch ----
__device__ int g_acnt[En];
__device__ int g_ccnt[Tn];
__device__ int g_alist[En * Bn];
__device__ int g_clist[Tn * Bn];
__device__ __nv_bfloat16 g_aw1h[En * Fn * Hn];
__device__ __nv_bfloat16 g_aw1l[En * Fn * Hn];
__device__ __nv_bfloat16 g_aw2h[En * Hn * An];
__device__ __nv_bfloat16 g_aw2l[En * Hn * An];
__device__ __nv_bfloat16 g_cw1h[Tn * Fn * HCn];
__device__ __nv_bfloat16 g_cw1l[Tn * Fn * HCn];

typedef wmma::fragment<wmma::matrix_a, 16, 16, 16, __nv_bfloat16, wmma::row_major> FragA;
typedef wmma::fragment<wmma::matrix_b, 16, 16, 16, __nv_bfloat16, wmma::row_major> FragB;
typedef wmma::fragment<wmma::accumulator, 16, 16, 16, float> FragC;

// ---------------- routing ----------------
__global__ void zero_kernel() {
    int t = threadIdx.x;
    if (t < En) g_acnt[t] = 0;
    if (t < Tn) g_ccnt[t] = 0;
}

__global__ void route_kernel(const int* __restrict__ commands,
                             const int* __restrict__ tasks) {
    __shared__ int scA[En], scC[Tn], baseA[En], baseC[Tn];
    int tid = threadIdx.x;
    if (tid < En) scA[tid] = 0;
    if (tid < Tn) scC[tid] = 0;
    __syncthreads();
    int b = blockIdx.x * blockDim.x + tid;
    int e = commands[b];
    int pa = atomicAdd(&scA[e], 1);
    int t = tasks[b];
    int pc = atomicAdd(&scC[t], 1);
    __syncthreads();
    if (tid < En) baseA[tid] = atomicAdd(&g_acnt[tid], scA[tid]);
    if (tid < Tn) baseC[tid] = atomicAdd(&g_ccnt[tid], scC[tid]);
    __syncthreads();
    g_alist[e * Bn + baseA[e] + pa] = b;
    g_clist[t * Bn + baseC[t] + pc] = b;
}

// ---------------- weight split prep ----------------
__global__ void prep_kernel(const float* __restrict__ AW1, const float* __restrict__ AW2,
                            const float* __restrict__ CW1) {
    int i = blockIdx.x * 256 + threadIdx.x;
    if (i < En * Fn * Hn) {
        float f = AW1[i];
        __nv_bfloat16 h = __float2bfloat16(f);
        g_aw1h[i] = h;
        g_aw1l[i] = __float2bfloat16(f - __bfloat162float(h));
    } else if (i < En * Fn * Hn + En * Hn * An) {
        int j = i - En * Fn * Hn;
        float f = AW2[j];
        __nv_bfloat16 h = __float2bfloat16(f);
        g_aw2h[j] = h;
        g_aw2l[j] = __float2bfloat16(f - __bfloat162float(h));
    } else if (i < En * Fn * Hn + En * Hn * An + Tn * Fn * HCn) {
        int j = i - En * Fn * Hn - En * Hn * An;
        float f = CW1[j];
        __nv_bfloat16 h = __float2bfloat16(f);
        g_cw1h[j] = h;
        g_cw1l[j] = __float2bfloat16(f - __bfloat162float(h));
    }
}

// ---------------- helpers ----------------
__device__ __forceinline__ uint32_t pk(float a, float b) {
    __nv_bfloat162 t = __floats2bfloat162_rn(a, b);
    return *reinterpret_cast<uint32_t*>(&t);
}

__device__ __forceinline__ void split8(const float* f, uint4& hi, uint4& lo) {
    float fh[8], fl[8];
#pragma unroll
    for (int i = 0; i < 8; i++) {
        float h = __bfloat162float(__float2bfloat16(f[i]));
        fh[i] = h;
        fl[i] = f[i] - h;
    }
    hi = make_uint4(pk(fh[0], fh[1]), pk(fh[2], fh[3]), pk(fh[4], fh[5]), pk(fh[6], fh[7]));
    lo = make_uint4(pk(fl[0], fl[1]), pk(fl[2], fl[3]), pk(fl[4], fl[5]), pk(fl[6], fl[7]));
}

__device__ __forceinline__ uint32_t s2u(const void* p) {
    return (uint32_t)__cvta_generic_to_shared(p);
}
__device__ __forceinline__ void cpa(uint32_t d, const void* s) {
    asm volatile("cp.async.cg.shared.global [%0], [%1], 16;" :: "r"(d), "l"(s));
}
#define CPC() asm volatile("cp.async.commit_group;")
#define CPW1() asm volatile("cp.async.wait_group 1;")
#define CPW0() asm volatile("cp.async.wait_group 0;")

// load 8 fp32 of this thread's row slice (16-col slice, lane pair splits 8/8)
__device__ __forceinline__ void ldx8(float* r, const float* __restrict__ x, int grow,
                                     int kc, int tid) {
    const float4* s = (const float4*)(x + (size_t)grow * Fn + kc * 16 + (tid & 1) * 8);
    float4 v;
    v = s[0]; r[0] = v.x; r[1] = v.y; r[2] = v.z; r[3] = v.w;
    v = s[1]; r[4] = v.x; r[5] = v.y; r[6] = v.z; r[7] = v.w;
}

// split regs, store into XS buffer b ([64][24] bf16, hi at +0, lo at +3072)
__device__ __forceinline__ void stx8(unsigned char* sm, int b, const float* r, int tid) {
    uint4 hi, lo;
    split8(r, hi, lo);
    uint32_t a = (uint32_t)((tid >> 1) * 48 + (tid & 1) * 16);
    *(uint4*)(sm + XS0 + b * 6144 + a) = hi;
    *(uint4*)(sm + XS0 + b * 6144 + 3072 + a) = lo;
}

// W1 slice kc16 (16 k-rows x 128 cols) -> BT buffer (hi +0, lo +4352, stride 272B)
__device__ __forceinline__ void issue_w1(unsigned char* sm, int b, int grp, int kc16, int tid) {
    int k = tid >> 3, seg = tid & 7;
    size_t gb = (((size_t)grp * Fn + kc16 * 16 + k) << 7) + seg * 16;
    uint32_t d = s2u(sm + BT0) + b * 8704 + k * 272 + seg * 32;
    cpa(d, g_aw1h + gb);
    cpa(d + 16, g_aw1h + gb + 8);
    cpa(d + 4352, g_aw1l + gb);
    cpa(d + 4352 + 16, g_aw1l + gb + 8);
}
// W2 slice kcg (0..15): N-half = kcg>>3, local k-slice = kcg&7
__device__ __forceinline__ void issue_w2(unsigned char* sm, int b, int grp, int kcg, int tid) {
    int k = tid >> 3, seg = tid & 7;
    size_t gb = ((size_t)grp * Hn + (kcg & 7) * 16 + k) * An + (kcg >> 3) * 128 + seg * 16;
    uint32_t d = s2u(sm + BT0) + b * 8704 + k * 272 + seg * 32;
    cpa(d, g_aw2h + gb);
    cpa(d + 16, g_aw2h + gb + 8);
    cpa(d + 4352, g_aw2l + gb);
    cpa(d + 4352 + 16, g_aw2l + gb + 8);
}
// critic W1 slice (16 x 32), buffer b at BT0 + b*2560 (hi 1280 stride 80B, lo +1280)
__device__ __forceinline__ void issue_cw(unsigned char* sm, int b, int grp, int kc16, int tid) {
    if (tid < 64) {
        int row = tid >> 2, seg = tid & 3;
        size_t gb = ((size_t)grp * Fn + kc16 * 16 + row) * HCn + seg * 8;
        uint32_t d = s2u(sm + BT0) + b * 2560 + row * 80 + seg * 16;
        cpa(d, g_cw1h + gb);
        cpa(d + 1280, g_cw1l + gb);
    }
}

// ---------------- fused actor + critic ----------------
extern "C" __global__ void __launch_bounds__(128, 3)
fused_kernel(const float* __restrict__ x, const int* __restrict__ actions,
             const float* __restrict__ Ab1, const float* __restrict__ Ab2,
             const float* __restrict__ Cb1, const float* __restrict__ CW2,
             const float* __restrict__ Cb2, float* __restrict__ out) {
    extern __shared__ unsigned char sm[];
    int tid = threadIdx.x;
    int wid = tid >> 5;
    int wm = wid >> 1;
    int wn = wid & 1;
    bool is_actor = (blockIdx.z == 0);

    int grp = -1, local = blockIdx.x;
    const int* cnts = is_actor ? g_acnt : g_ccnt;
#pragma unroll
    for (int i = 0; i < En; i++) {
        int nt = (cnts[i] + MT - 1) / MT;
        if (grp < 0) {
            if (local < nt) grp = i;
            else local -= nt;
        }
    }
    if (grp < 0) return;
    int cnt = cnts[grp];
    int r0 = local * MT;

    int* ridx = (int*)(sm + RIDX);
    int* acts = (int*)(sm + ACTS);
    if (tid < MT) {
        int r = r0 + tid;
        const int* list = is_actor ? (g_alist + grp * Bn) : (g_clist + grp * Bn);
        int idx = (r < cnt) ? list[r] : -1;
        ridx[tid] = idx;
        if (is_actor) acts[tid] = (idx >= 0) ? actions[idx] : 0;
    }
    if (is_actor) {
        ((float*)(sm + AB1))[tid] = Ab1[grp * Hn + tid];
        ((float*)(sm + AB2))[tid] = Ab2[grp * An + tid];
        ((float*)(sm + AB2))[128 + tid] = Ab2[grp * An + 128 + tid];
    } else if (tid < HCn) {
        ((float*)(sm + CB1))[tid] = Cb1[grp * HCn + tid];
        ((float*)(sm + CW2S))[tid] = CW2[grp * HCn + tid];
    }
    __syncthreads();
    int rr = ridx[tid >> 1];
    int grow = rr < 0 ? 0 : rr;
    float xr[8];
    float* stg = (float*)(sm + XS0);  // f32 staging [64][36] over dead XS region

    if (is_actor) {
        // ======== GEMM1: h = x @ W1 [64 x 512 x 128], K-slice 16, pipelined ====
        FragC acc[2][4];
#pragma unroll
        for (int mi = 0; mi < 2; mi++)
#pragma unroll
            for (int ni = 0; ni < 4; ni++) wmma::fill_fragment(acc[mi][ni], 0.f);

        ldx8(xr, x, grow, 0, tid);
        stx8(sm, 0, xr, tid);
        ldx8(xr, x, grow, 1, tid);
        issue_w1(sm, 0, grp, 0, tid);
        CPC();

        for (int kc = 0; kc < 32; kc++) {
            int b = kc & 1;
            // (A): all threads finished reading BT[b^1] (at kc-1) before refilling it
            __syncthreads();
            if (kc < 31) issue_w1(sm, b ^ 1, grp, kc + 1, tid);
            else issue_w2(sm, 0, grp, 0, tid);  // prefetch GEMM2 kcg0 -> buf0
            CPC();
            CPW1();  // own portion of BT[b] group complete; next group in flight
            // (B): cross-thread visibility of BT[b] + XS[b]
            __syncthreads();
            const __nv_bfloat16* xh = (const __nv_bfloat16*)(sm + XS0 + b * 6144);
            const __nv_bfloat16* bh = (const __nv_bfloat16*)(sm + BT0 + b * 8704);
            FragA ah[2], al[2];
#pragma unroll
            for (int mi = 0; mi < 2; mi++) {
                wmma::load_matrix_sync(ah[mi], xh + (wm * 32 + mi * 16) * 24, 24);
                wmma::load_matrix_sync(al[mi], xh + 1536 + (wm * 32 + mi * 16) * 24, 24);
            }
#pragma unroll
            for (int ni = 0; ni < 4; ni++) {
                FragB fbh, fbl;
                wmma::load_matrix_sync(fbh, bh + wn * 64 + ni * 16, 136);
                wmma::load_matrix_sync(fbl, bh + 2176 + wn * 64 + ni * 16, 136);
#pragma unroll
                for (int mi = 0; mi < 2; mi++) {
                    wmma::mma_sync(acc[mi][ni], ah[mi], fbh, acc[mi][ni]);
                    wmma::mma_sync(acc[mi][ni], ah[mi], fbl, acc[mi][ni]);
                    wmma::mma_sync(acc[mi][ni], al[mi], fbh, acc[mi][ni]);
                }
            }
            if (kc < 31) {
                stx8(sm, b ^ 1, xr, tid);  // consumed at kc+1 after its (B)
                if (kc < 30) ldx8(xr, x, grow, kc + 2, tid);
            }
        }

        // ---- GEMM1 epilogue: 4 passes of 32 cols via XS staging ----
        __syncthreads();
#pragma unroll 1
        for (int p = 0; p < 4; p++) {
            if (wn == (p >> 1)) {
                int j0 = (p & 1) * 2;
#pragma unroll
                for (int mi = 0; mi < 2; mi++)
#pragma unroll
                    for (int j = 0; j < 2; j++)
                        wmma::store_matrix_sync(stg + (wm * 32 + mi * 16) * 36 + j * 16,
                                                acc[mi][j0 + j], 36, wmma::mem_row_major);
            }
            __syncthreads();
            int row = tid >> 1, cl = (tid & 1) * 16;
            const float* sp = stg + row * 36 + cl;
            const float* bp = (const float*)(sm + AB1) + p * 32 + cl;
#pragma unroll
            for (int g = 0; g < 2; g++) {
                float f[8];
#pragma unroll
                for (int i = 0; i < 8; i++) {
                    float h = sp[g * 8 + i] + bp[g * 8 + i];
                    f[i] = h > 0.f ? h : 0.f;
                }
                uint4 hi, lo;
                split8(f, hi, lo);
                *(uint4*)(sm + HH + (row * 136 + p * 32 + cl + g * 8) * 2) = hi;
                *(uint4*)(sm + HL + (row * 136 + p * 32 + cl + g * 8) * 2) = lo;
            }
            __syncthreads();
        }

        // ======== GEMM2: scores = h @ W2, K-slice 16, online softmax ========
        float mrun = -3e38f, zrun = 0.f, s1run = 0.f, schrun = -3e38f;
        int myact = acts[tid >> 1];
        FragC a2[2][4];
#pragma unroll 1
        for (int half = 0; half < 2; half++) {
#pragma unroll
            for (int mi = 0; mi < 2; mi++)
#pragma unroll
                for (int ni = 0; ni < 4; ni++) wmma::fill_fragment(a2[mi][ni], 0.f);
#pragma unroll 1
            for (int kcl = 0; kcl < 8; kcl++) {
                int kcg = half * 8 + kcl;
                int b = kcg & 1;
                // (A): previous consumers of BT[b^1] done before refill
                __syncthreads();
                if (kcg < 15) {
                    issue_w2(sm, b ^ 1, grp, kcg + 1, tid);
                    CPC();
                    CPW1();
                } else {
                    CPW0();
                }
                // (B): cross-thread visibility of BT[b]
                __syncthreads();
                const __nv_bfloat16* bh = (const __nv_bfloat16*)(sm + BT0 + b * 8704);
                FragA ah[2], al[2];
#pragma unroll
                for (int mi = 0; mi < 2; mi++) {
                    wmma::load_matrix_sync(ah[mi], (const __nv_bfloat16*)(sm + HH) +
                        (wm * 32 + mi * 16) * 136 + kcl * 16, 136);
                    wmma::load_matrix_sync(al[mi], (const __nv_bfloat16*)(sm + HL) +
                        (wm * 32 + mi * 16) * 136 + kcl * 16, 136);
                }
#pragma unroll
                for (int ni = 0; ni < 4; ni++) {
                    FragB fbh, fbl;
                    wmma::load_matrix_sync(fbh, bh + wn * 64 + ni * 16, 136);
                    wmma::load_matrix_sync(fbl, bh + 2176 + wn * 64 + ni * 16, 136);
#pragma unroll
                    for (int mi = 0; mi < 2; mi++) {
                        wmma::mma_sync(a2[mi][ni], ah[mi], fbh, a2[mi][ni]);
                        wmma::mma_sync(a2[mi][ni], ah[mi], fbl, a2[mi][ni]);
                        wmma::mma_sync(a2[mi][ni], al[mi], fbh, a2[mi][ni]);
                    }
                }
            }
            // ---- half epilogue: 4 passes of 32 cols via XS staging ----
            __syncthreads();
#pragma unroll 1
            for (int p = 0; p < 4; p++) {
                if (wn == (p >> 1)) {
                    int j0 = (p & 1) * 2;
#pragma unroll
                    for (int mi = 0; mi < 2; mi++)
#pragma unroll
                        for (int j = 0; j < 2; j++)
                            wmma::store_matrix_sync(stg + (wm * 32 + mi * 16) * 36 + j * 16,
                                                    a2[mi][j0 + j], 36, wmma::mem_row_major);
                }
                __syncthreads();
                int row = tid >> 1, cl = (tid & 1) * 16;
                int abase = half * 128 + p * 32 + cl;
                const float* sp = stg + row * 36 + cl;
                const float* bp = (const float*)(sm + AB2) + abase;
                float s[16];
                float mx = -3e38f;
#pragma unroll
                for (int c = 0; c < 16; c++) {
                    s[c] = sp[c] + bp[c];
                    mx = fmaxf(mx, s[c]);
                }
                float z = 0.f, s1 = 0.f, sch = -3e38f;
#pragma unroll
                for (int c = 0; c < 16; c++) {
                    float pv = __expf(s[c] - mx);
                    z += pv;
                    s1 += s[c] * pv;
                    if (abase + c == myact) sch = s[c];
                }
                float mo = __shfl_xor_sync(0xffffffffu, mx, 1);
                float zo = __shfl_xor_sync(0xffffffffu, z, 1);
                float so = __shfl_xor_sync(0xffffffffu, s1, 1);
                float co = __shfl_xor_sync(0xffffffffu, sch, 1);
                float M = fmaxf(mx, mo);
                float f1 = __expf(mx - M), f2 = __expf(mo - M);
                z = z * f1 + zo * f2;
                s1 = s1 * f1 + so * f2;
                sch = fmaxf(sch, co);
                float MM = fmaxf(mrun, M);
                float g1 = __expf(mrun - MM), g2 = __expf(M - MM);
                zrun = zrun * g1 + z * g2;
                s1run = s1run * g1 + s1 * g2;
                mrun = MM;
                schrun = fmaxf(schrun, sch);
                __syncthreads();
            }
        }
        {
            int row = tid >> 1;
            if ((tid & 1) == 0 && r0 + row < cnt) {
                int b = ridx[row];
                float lz = mrun + __logf(zrun);
                out[(size_t)b * 3 + 0] = schrun - lz;
                out[(size_t)b * 3 + 2] = s1run / zrun - lz;
            }
        }
    } else {
        // ======== Critic [64 x 512 x 32], K-slice 16, pipelined ========
        FragC acc[2];
        wmma::fill_fragment(acc[0], 0.f);
        wmma::fill_fragment(acc[1], 0.f);

        ldx8(xr, x, grow, 0, tid);
        stx8(sm, 0, xr, tid);
        ldx8(xr, x, grow, 1, tid);
        issue_cw(sm, 0, grp, 0, tid);
        CPC();

        for (int kc = 0; kc < 32; kc++) {
            int b = kc & 1;
            __syncthreads();  // (A)
            if (kc < 31) {
                issue_cw(sm, b ^ 1, grp, kc + 1, tid);
                CPC();
                CPW1();
            } else {
                CPW0();
            }
            __syncthreads();  // (B)
            const __nv_bfloat16* xh = (const __nv_bfloat16*)(sm + XS0 + b * 6144);
            const __nv_bfloat16* bh = (const __nv_bfloat16*)(sm + BT0 + b * 2560);
            FragA ah[2], al[2];
#pragma unroll
            for (int mi = 0; mi < 2; mi++) {
                wmma::load_matrix_sync(ah[mi], xh + (wm * 32 + mi * 16) * 24, 24);
                wmma::load_matrix_sync(al[mi], xh + 1536 + (wm * 32 + mi * 16) * 24, 24);
            }
            FragB fbh, fbl;
            wmma::load_matrix_sync(fbh, bh + wn * 16, 40);
            wmma::load_matrix_sync(fbl, bh + 640 + wn * 16, 40);
#pragma unroll
            for (int mi = 0; mi < 2; mi++) {
                wmma::mma_sync(acc[mi], ah[mi], fbh, acc[mi]);
                wmma::mma_sync(acc[mi], ah[mi], fbl, acc[mi]);
                wmma::mma_sync(acc[mi], al[mi], fbh, acc[mi]);
            }
            if (kc < 31) {
                stx8(sm, b ^ 1, xr, tid);
                if (kc < 30) ldx8(xr, x, grow, kc + 2, tid);
            }
        }
        __syncthreads();
#pragma unroll
        for (int mi = 0; mi < 2; mi++)
            wmma::store_matrix_sync(stg + (wm * 32 + mi * 16) * 36 + wn * 16, acc[mi], 36,
                                    wmma::mem_row_major);
        __syncthreads();
        {
            int row = tid >> 1, c0 = (tid & 1) * 16;
            const float4* hp = (const float4*)(stg + row * 36 + c0);
            const float4* b1p = (const float4*)((float*)(sm + CB1) + c0);
            const float4* w2p = (const float4*)((float*)(sm + CW2S) + c0);
            float sum = 0.f;
#pragma unroll
            for (int g = 0; g < 4; g++) {
                float4 h4 = hp[g], b4 = b1p[g], w4 = w2p[g];
                float h;
                h = h4.x + b4.x; sum += (h > 0.f ? h : 0.f) * w4.x;
                h = h4.y + b4.y; sum += (h > 0.f ? h : 0.f) * w4.y;
                h = h4.z + b4.z; sum += (h > 0.f ? h : 0.f) * w4.z;
                h = h4.w + b4.w; sum += (h > 0.f ? h : 0.f) * w4.w;
            }
            sum += __shfl_xor_sync(0xffffffffu, sum, 1);
            if ((tid & 1) == 0 && r0 + row < cnt)
                out[(size_t)ridx[row] * 3 + 1] = sum + Cb2[grp];
        }
    }
}

extern "C" void kernel_launch(void* const* d_in, const int* in_sizes, int n_in,
                              void* d_out, int out_size) {
    const float* x = (const float*)d_in[0];
    const int* commands = (const int*)d_in[1];
    const int* tasks = (const int*)d_in[2];
    const int* actions = (const int*)d_in[3];
    const float* A_W1 = (const float*)d_in[4];
    const float* A_b1 = (const float*)d_in[5];
    const float* A_W2 = (const float*)d_in[6];
    const float* A_b2 = (const float*)d_in[7];
    const float* C_W1 = (const float*)d_in[8];
    const float* C_b1 = (const float*)d_in[9];
    const float* C_W2 = (const float*)d_in[10];
    const float* C_b2 = (const float*)d_in[11];
    float* out = (float*)d_out;

    cudaFuncSetAttribute(fused_kernel, cudaFuncAttributeMaxDynamicSharedMemorySize,
                         SMEM_TOTAL);

    zero_kernel<<<1, 32>>>();
    route_kernel<<<Bn / 256, 256>>>(commands, tasks);
    int prep_elems = En * Fn * Hn + En * Hn * An + Tn * Fn * HCn;
    prep_kernel<<<(prep_elems + 255) / 256, 256>>>(A_W1, A_W2, C_W1);
    fused_kernel<<<dim3(NTILES_MAX, 1, 2), 128, SMEM_TOTAL>>>(
        x, actions, A_b1, A_b2, C_b1, C_W2, C_b2, out);
}

// round 11
// speedup vs baseline: 2.4708x; 1.0787x over previous
#include <cuda_runtime.h>
#include <cuda_bf16.h>
#include <mma.h>
#include <cstdint>

using namespace nvcuda;

#define Bn 32768
#define Fn 512
#define En 8
#define Hn 128
#define An 256
#define Tn 8
#define HCn 32
#define MT 64
#define NTILES_MAX 520

// ---- smem layout (bytes) ----
#define XS0   0         // 2 x 6144 x tiles ([64][24] bf16 hi + lo); doubles as f32 staging
#define BT0   12288     // weight tile buffers: 2 x 8704 ([16][136] bf16 hi at +0, lo at +4352)
#define HH    29696     // [64][136] bf16 (17408) -- h hi only (2-term GEMM2)
#define RIDX  47104
#define ACTS  47360
#define AB1   47616
#define AB2   48128
#define CB1   49152
#define CW2S  49280
#define SMEM_TOTAL 49408

// ---- device scratch ----
__device__ int g_acnt[En];
__device__ int g_ccnt[Tn];
__device__ int g_alist[En * Bn];
__device__ int g_clist[Tn * Bn];
__device__ __nv_bfloat16 g_aw1h[En * Fn * Hn];
__device__ __nv_bfloat16 g_aw1l[En * Fn * Hn];
__device__ __nv_bfloat16 g_aw2h[En * Hn * An];
__device__ __nv_bfloat16 g_aw2l[En * Hn * An];
__device__ __nv_bfloat16 g_cw1h[Tn * Fn * HCn];
__device__ __nv_bfloat16 g_cw1l[Tn * Fn * HCn];

typedef wmma::fragment<wmma::matrix_a, 16, 16, 16, __nv_bfloat16, wmma::row_major> FragA;
typedef wmma::fragment<wmma::matrix_b, 16, 16, 16, __nv_bfloat16, wmma::row_major> FragB;
typedef wmma::fragment<wmma::accumulator, 16, 16, 16, float> FragC;

// ---------------- routing ----------------
__global__ void zero_kernel() {
    int t = threadIdx.x;
    if (t < En) g_acnt[t] = 0;
    if (t < Tn) g_ccnt[t] = 0;
}

__global__ void route_kernel(const int* __restrict__ commands,
                             const int* __restrict__ tasks) {
    __shared__ int scA[En], scC[Tn], baseA[En], baseC[Tn];
    int tid = threadIdx.x;
    if (tid < En) scA[tid] = 0;
    if (tid < Tn) scC[tid] = 0;
    __syncthreads();
    int b = blockIdx.x * blockDim.x + tid;
    int e = commands[b];
    int pa = atomicAdd(&scA[e], 1);
    int t = tasks[b];
    int pc = atomicAdd(&scC[t], 1);
    __syncthreads();
    if (tid < En) baseA[tid] = atomicAdd(&g_acnt[tid], scA[tid]);
    if (tid < Tn) baseC[tid] = atomicAdd(&g_ccnt[tid], scC[tid]);
    __syncthreads();
    g_alist[e * Bn + baseA[e] + pa] = b;
    g_clist[t * Bn + baseC[t] + pc] = b;
}

// ---------------- weight split prep ----------------
__global__ void prep_kernel(const float* __restrict__ AW1, const float* __restrict__ AW2,
                            const float* __restrict__ CW1) {
    int i = blockIdx.x * 256 + threadIdx.x;
    if (i < En * Fn * Hn) {
        float f = AW1[i];
        __nv_bfloat16 h = __float2bfloat16(f);
        g_aw1h[i] = h;
        g_aw1l[i] = __float2bfloat16(f - __bfloat162float(h));
    } else if (i < En * Fn * Hn + En * Hn * An) {
        int j = i - En * Fn * Hn;
        float f = AW2[j];
        __nv_bfloat16 h = __float2bfloat16(f);
        g_aw2h[j] = h;
        g_aw2l[j] = __float2bfloat16(f - __bfloat162float(h));
    } else if (i < En * Fn * Hn + En * Hn * An + Tn * Fn * HCn) {
        int j = i - En * Fn * Hn - En * Hn * An;
        float f = CW1[j];
        __nv_bfloat16 h = __float2bfloat16(f);
        g_cw1h[j] = h;
        g_cw1l[j] = __float2bfloat16(f - __bfloat162float(h));
    }
}

// ---------------- helpers ----------------
__device__ __forceinline__ uint32_t pk(float a, float b) {
    __nv_bfloat162 t = __floats2bfloat162_rn(a, b);
    return *reinterpret_cast<uint32_t*>(&t);
}

__device__ __forceinline__ void split8(const float* f, uint4& hi, uint4& lo) {
    float fh[8], fl[8];
#pragma unroll
    for (int i = 0; i < 8; i++) {
        float h = __bfloat162float(__float2bfloat16(f[i]));
        fh[i] = h;
        fl[i] = f[i] - h;
    }
    hi = make_uint4(pk(fh[0], fh[1]), pk(fh[2], fh[3]), pk(fh[4], fh[5]), pk(fh[6], fh[7]));
    lo = make_uint4(pk(fl[0], fl[1]), pk(fl[2], fl[3]), pk(fl[4], fl[5]), pk(fl[6], fl[7]));
}

__device__ __forceinline__ uint32_t s2u(const void* p) {
    return (uint32_t)__cvta_generic_to_shared(p);
}
__device__ __forceinline__ void cpa(uint32_t d, const void* s) {
    asm volatile("cp.async.cg.shared.global [%0], [%1], 16;" :: "r"(d), "l"(s));
}
#define CPC() asm volatile("cp.async.commit_group;")
#define CPW1() asm volatile("cp.async.wait_group 1;")
#define CPW0() asm volatile("cp.async.wait_group 0;")

// load 8 fp32 of this thread's row slice (16-col slice, lane pair splits 8/8)
__device__ __forceinline__ void ldx8(float* r, const float* __restrict__ x, int grow,
                                     int kc, int tid) {
    const float4* s = (const float4*)(x + (size_t)grow * Fn + kc * 16 + (tid & 1) * 8);
    float4 v;
    v = s[0]; r[0] = v.x; r[1] = v.y; r[2] = v.z; r[3] = v.w;
    v = s[1]; r[4] = v.x; r[5] = v.y; r[6] = v.z; r[7] = v.w;
}

// split regs, store into XS buffer b ([64][24] bf16, hi at +0, lo at +3072)
__device__ __forceinline__ void stx8(unsigned char* sm, int b, const float* r, int tid) {
    uint4 hi, lo;
    split8(r, hi, lo);
    uint32_t a = (uint32_t)((tid >> 1) * 48 + (tid & 1) * 16);
    *(uint4*)(sm + XS0 + b * 6144 + a) = hi;
    *(uint4*)(sm + XS0 + b * 6144 + 3072 + a) = lo;
}

// W1 slice kc16 (16 k-rows x 128 cols) -> BT buffer (hi +0, lo +4352, stride 272B)
__device__ __forceinline__ void issue_w1(unsigned char* sm, int b, int grp, int kc16, int tid) {
    int k = tid >> 3, seg = tid & 7;
    size_t gb = (((size_t)grp * Fn + kc16 * 16 + k) << 7) + seg * 16;
    uint32_t d = s2u(sm + BT0) + b * 8704 + k * 272 + seg * 32;
    cpa(d, g_aw1h + gb);
    cpa(d + 16, g_aw1h + gb + 8);
    cpa(d + 4352, g_aw1l + gb);
    cpa(d + 4352 + 16, g_aw1l + gb + 8);
}
// W2 slice kcg (0..15): N-half = kcg>>3, local k-slice = kcg&7
__device__ __forceinline__ void issue_w2(unsigned char* sm, int b, int grp, int kcg, int tid) {
    int k = tid >> 3, seg = tid & 7;
    size_t gb = ((size_t)grp * Hn + (kcg & 7) * 16 + k) * An + (kcg >> 3) * 128 + seg * 16;
    uint32_t d = s2u(sm + BT0) + b * 8704 + k * 272 + seg * 32;
    cpa(d, g_aw2h + gb);
    cpa(d + 16, g_aw2h + gb + 8);
    cpa(d + 4352, g_aw2l + gb);
    cpa(d + 4352 + 16, g_aw2l + gb + 8);
}
// critic W1 slice (16 x 32), buffer b at BT0 + b*2560 (hi 1280 stride 80B, lo +1280)
__device__ __forceinline__ void issue_cw(unsigned char* sm, int b, int grp, int kc16, int tid) {
    if (tid < 64) {
        int row = tid >> 2, seg = tid & 3;
        size_t gb = ((size_t)grp * Fn + kc16 * 16 + row) * HCn + seg * 8;
        uint32_t d = s2u(sm + BT0) + b * 2560 + row * 80 + seg * 16;
        cpa(d, g_cw1h + gb);
        cpa(d + 1280, g_cw1l + gb);
    }
}

// ---------------- fused actor + critic ----------------
extern "C" __global__ void __launch_bounds__(128, 4)
fused_kernel(const float* __restrict__ x, const int* __restrict__ actions,
             const float* __restrict__ Ab1, const float* __restrict__ Ab2,
             const float* __restrict__ Cb1, const float* __restrict__ CW2,
             const float* __restrict__ Cb2, float* __restrict__ out) {
    extern __shared__ unsigned char sm[];
    int tid = threadIdx.x;
    int wid = tid >> 5;
    int wm = wid >> 1;
    int wn = wid & 1;
    bool is_actor = (blockIdx.z == 0);

    int grp = -1, local = blockIdx.x;
    const int* cnts = is_actor ? g_acnt : g_ccnt;
#pragma unroll
    for (int i = 0; i < En; i++) {
        int nt = (cnts[i] + MT - 1) / MT;
        if (grp < 0) {
            if (local < nt) grp = i;
            else local -= nt;
        }
    }
    if (grp < 0) return;
    int cnt = cnts[grp];
    int r0 = local * MT;

    int* ridx = (int*)(sm + RIDX);
    int* acts = (int*)(sm + ACTS);
    if (tid < MT) {
        int r = r0 + tid;
        const int* list = is_actor ? (g_alist + grp * Bn) : (g_clist + grp * Bn);
        int idx = (r < cnt) ? list[r] : -1;
        ridx[tid] = idx;
        if (is_actor) acts[tid] = (idx >= 0) ? actions[idx] : 0;
    }
    if (is_actor) {
        ((float*)(sm + AB1))[tid] = Ab1[grp * Hn + tid];
        ((float*)(sm + AB2))[tid] = Ab2[grp * An + tid];
        ((float*)(sm + AB2))[128 + tid] = Ab2[grp * An + 128 + tid];
    } else if (tid < HCn) {
        ((float*)(sm + CB1))[tid] = Cb1[grp * HCn + tid];
        ((float*)(sm + CW2S))[tid] = CW2[grp * HCn + tid];
    }
    __syncthreads();
    int rr = ridx[tid >> 1];
    int grow = rr < 0 ? 0 : rr;
    float xr[8];
    float* stg = (float*)(sm + XS0);  // f32 staging [64][36] over dead XS region

    if (is_actor) {
        // ======== GEMM1: h = x @ W1 [64 x 512 x 128], K-slice 16, pipelined ====
        FragC acc[2][4];
#pragma unroll
        for (int mi = 0; mi < 2; mi++)
#pragma unroll
            for (int ni = 0; ni < 4; ni++) wmma::fill_fragment(acc[mi][ni], 0.f);

        ldx8(xr, x, grow, 0, tid);
        stx8(sm, 0, xr, tid);
        ldx8(xr, x, grow, 1, tid);
        issue_w1(sm, 0, grp, 0, tid);
        CPC();

        for (int kc = 0; kc < 32; kc++) {
            int b = kc & 1;
            // (A): all threads finished reading BT[b^1] (at kc-1) before refilling it
            __syncthreads();
            if (kc < 31) issue_w1(sm, b ^ 1, grp, kc + 1, tid);
            else issue_w2(sm, 0, grp, 0, tid);  // prefetch GEMM2 kcg0 -> buf0
            CPC();
            CPW1();  // own portion of BT[b] group complete; next group in flight
            // (B): cross-thread visibility of BT[b] + XS[b]
            __syncthreads();
            const __nv_bfloat16* xh = (const __nv_bfloat16*)(sm + XS0 + b * 6144);
            const __nv_bfloat16* bh = (const __nv_bfloat16*)(sm + BT0 + b * 8704);
            FragA ah[2], al[2];
#pragma unroll
            for (int mi = 0; mi < 2; mi++) {
                wmma::load_matrix_sync(ah[mi], xh + (wm * 32 + mi * 16) * 24, 24);
                wmma::load_matrix_sync(al[mi], xh + 1536 + (wm * 32 + mi * 16) * 24, 24);
            }
#pragma unroll
            for (int ni = 0; ni < 4; ni++) {
                FragB fbh, fbl;
                wmma::load_matrix_sync(fbh, bh + wn * 64 + ni * 16, 136);
                wmma::load_matrix_sync(fbl, bh + 2176 + wn * 64 + ni * 16, 136);
#pragma unroll
                for (int mi = 0; mi < 2; mi++) {
                    wmma::mma_sync(acc[mi][ni], ah[mi], fbh, acc[mi][ni]);
                    wmma::mma_sync(acc[mi][ni], ah[mi], fbl, acc[mi][ni]);
                    wmma::mma_sync(acc[mi][ni], al[mi], fbh, acc[mi][ni]);
                }
            }
            if (kc < 31) {
                stx8(sm, b ^ 1, xr, tid);  // consumed at kc+1 after its (B)
                if (kc < 30) ldx8(xr, x, grow, kc + 2, tid);
            }
        }

        // ---- GEMM1 epilogue: 4 passes of 32 cols via XS staging; h hi only ----
        __syncthreads();
#pragma unroll 1
        for (int p = 0; p < 4; p++) {
            if (wn == (p >> 1)) {
                int j0 = (p & 1) * 2;
#pragma unroll
                for (int mi = 0; mi < 2; mi++)
#pragma unroll
                    for (int j = 0; j < 2; j++)
                        wmma::store_matrix_sync(stg + (wm * 32 + mi * 16) * 36 + j * 16,
                                                acc[mi][j0 + j], 36, wmma::mem_row_major);
            }
            __syncthreads();
            int row = tid >> 1, cl = (tid & 1) * 16;
            const float* sp = stg + row * 36 + cl;
            const float* bp = (const float*)(sm + AB1) + p * 32 + cl;
#pragma unroll
            for (int g = 0; g < 2; g++) {
                float f[8];
#pragma unroll
                for (int i = 0; i < 8; i++) {
                    float h = sp[g * 8 + i] + bp[g * 8 + i];
                    f[i] = h > 0.f ? h : 0.f;
                }
                uint4 hi = make_uint4(pk(f[0], f[1]), pk(f[2], f[3]),
                                      pk(f[4], f[5]), pk(f[6], f[7]));
                *(uint4*)(sm + HH + (row * 136 + p * 32 + cl + g * 8) * 2) = hi;
            }
            __syncthreads();
        }

        // ======== GEMM2: scores = h_hi @ (W2h + W2l), 2-term, online softmax ===
        float mrun = -3e38f, zrun = 0.f, s1run = 0.f, schrun = -3e38f;
        int myact = acts[tid >> 1];
        FragC a2[2][4];
#pragma unroll 1
        for (int half = 0; half < 2; half++) {
#pragma unroll
            for (int mi = 0; mi < 2; mi++)
#pragma unroll
                for (int ni = 0; ni < 4; ni++) wmma::fill_fragment(a2[mi][ni], 0.f);
#pragma unroll 1
            for (int kcl = 0; kcl < 8; kcl++) {
                int kcg = half * 8 + kcl;
                int b = kcg & 1;
                // (A): previous consumers of BT[b^1] done before refill
                __syncthreads();
                if (kcg < 15) {
                    issue_w2(sm, b ^ 1, grp, kcg + 1, tid);
                    CPC();
                    CPW1();
                } else {
                    CPW0();
                }
                // (B): cross-thread visibility of BT[b]
                __syncthreads();
                const __nv_bfloat16* bh = (const __nv_bfloat16*)(sm + BT0 + b * 8704);
                FragA ah[2];
#pragma unroll
                for (int mi = 0; mi < 2; mi++)
                    wmma::load_matrix_sync(ah[mi], (const __nv_bfloat16*)(sm + HH) +
                        (wm * 32 + mi * 16) * 136 + kcl * 16, 136);
#pragma unroll
                for (int ni = 0; ni < 4; ni++) {
                    FragB fbh, fbl;
                    wmma::load_matrix_sync(fbh, bh + wn * 64 + ni * 16, 136);
                    wmma::load_matrix_sync(fbl, bh + 2176 + wn * 64 + ni * 16, 136);
#pragma unroll
                    for (int mi = 0; mi < 2; mi++) {
                        wmma::mma_sync(a2[mi][ni], ah[mi], fbh, a2[mi][ni]);
                        wmma::mma_sync(a2[mi][ni], ah[mi], fbl, a2[mi][ni]);
                    }
                }
            }
            // ---- half epilogue: 4 passes of 32 cols via XS staging ----
            __syncthreads();
#pragma unroll 1
            for (int p = 0; p < 4; p++) {
                if (wn == (p >> 1)) {
                    int j0 = (p & 1) * 2;
#pragma unroll
                    for (int mi = 0; mi < 2; mi++)
#pragma unroll
                        for (int j = 0; j < 2; j++)
                            wmma::store_matrix_sync(stg + (wm * 32 + mi * 16) * 36 + j * 16,
                                                    a2[mi][j0 + j], 36, wmma::mem_row_major);
                }
                __syncthreads();
                int row = tid >> 1, cl = (tid & 1) * 16;
                int abase = half * 128 + p * 32 + cl;
                const float* sp = stg + row * 36 + cl;
                const float* bp = (const float*)(sm + AB2) + abase;
                float s[16];
                float mx = -3e38f;
#pragma unroll
                for (int c = 0; c < 16; c++) {
                    s[c] = sp[c] + bp[c];
                    mx = fmaxf(mx, s[c]);
                }
                float z = 0.f, s1 = 0.f, sch = -3e38f;
#pragma unroll
                for (int c = 0; c < 16; c++) {
                    float pv = __expf(s[c] - mx);
                    z += pv;
                    s1 += s[c] * pv;
                    if (abase + c == myact) sch = s[c];
                }
                float mo = __shfl_xor_sync(0xffffffffu, mx, 1);
                float zo = __shfl_xor_sync(0xffffffffu, z, 1);
                float so = __shfl_xor_sync(0xffffffffu, s1, 1);
                float co = __shfl_xor_sync(0xffffffffu, sch, 1);
                float M = fmaxf(mx, mo);
                float f1 = __expf(mx - M), f2 = __expf(mo - M);
                z = z * f1 + zo * f2;
                s1 = s1 * f1 + so * f2;
                sch = fmaxf(sch, co);
                float MM = fmaxf(mrun, M);
                float g1 = __expf(mrun - MM), g2 = __expf(M - MM);
                zrun = zrun * g1 + z * g2;
                s1run = s1run * g1 + s1 * g2;
                mrun = MM;
                schrun = fmaxf(schrun, sch);
                __syncthreads();
            }
        }
        {
            int row = tid >> 1;
            if ((tid & 1) == 0 && r0 + row < cnt) {
                int b = ridx[row];
                float lz = mrun + __logf(zrun);
                out[(size_t)b * 3 + 0] = schrun - lz;
                out[(size_t)b * 3 + 2] = s1run / zrun - lz;
            }
        }
    } else {
        // ======== Critic [64 x 512 x 32], K-slice 16, 3-term, pipelined ========
        FragC acc[2];
        wmma::fill_fragment(acc[0], 0.f);
        wmma::fill_fragment(acc[1], 0.f);

        ldx8(xr, x, grow, 0, tid);
        stx8(sm, 0, xr, tid);
        ldx8(xr, x, grow, 1, tid);
        issue_cw(sm, 0, grp, 0, tid);
        CPC();

        for (int kc = 0; kc < 32; kc++) {
            int b = kc & 1;
            __syncthreads();  // (A)
            if (kc < 31) {
                issue_cw(sm, b ^ 1, grp, kc + 1, tid);
                CPC();
                CPW1();
            } else {
                CPW0();
            }
            __syncthreads();  // (B)
            const __nv_bfloat16* xh = (const __nv_bfloat16*)(sm + XS0 + b * 6144);
            const __nv_bfloat16* bh = (const __nv_bfloat16*)(sm + BT0 + b * 2560);
            FragA ah[2], al[2];
#pragma unroll
            for (int mi = 0; mi < 2; mi++) {
                wmma::load_matrix_sync(ah[mi], xh + (wm * 32 + mi * 16) * 24, 24);
                wmma::load_matrix_sync(al[mi], xh + 1536 + (wm * 32 + mi * 16) * 24, 24);
            }
            FragB fbh, fbl;
            wmma::load_matrix_sync(fbh, bh + wn * 16, 40);
            wmma::load_matrix_sync(fbl, bh + 640 + wn * 16, 40);
#pragma unroll
            for (int mi = 0; mi < 2; mi++) {
                wmma::mma_sync(acc[mi], ah[mi], fbh, acc[mi]);
                wmma::mma_sync(acc[mi], ah[mi], fbl, acc[mi]);
                wmma::mma_sync(acc[mi], al[mi], fbh, acc[mi]);
            }
            if (kc < 31) {
                stx8(sm, b ^ 1, xr, tid);
                if (kc < 30) ldx8(xr, x, grow, kc + 2, tid);
            }
        }
        __syncthreads();
#pragma unroll
        for (int mi = 0; mi < 2; mi++)
            wmma::store_matrix_sync(stg + (wm * 32 + mi * 16) * 36 + wn * 16, acc[mi], 36,
                                    wmma::mem_row_major);
        __syncthreads();
        {
            int row = tid >> 1, c0 = (tid & 1) * 16;
            const float4* hp = (const float4*)(stg + row * 36 + c0);
            const float4* b1p = (const float4*)((float*)(sm + CB1) + c0);
            const float4* w2p = (const float4*)((float*)(sm + CW2S) + c0);
            float sum = 0.f;
#pragma unroll
            for (int g = 0; g < 4; g++) {
                float4 h4 = hp[g], b4 = b1p[g], w4 = w2p[g];
                float h;
                h = h4.x + b4.x; sum += (h > 0.f ? h : 0.f) * w4.x;
                h = h4.y + b4.y; sum += (h > 0.f ? h : 0.f) * w4.y;
                h = h4.z + b4.z; sum += (h > 0.f ? h : 0.f) * w4.z;
                h = h4.w + b4.w; sum += (h > 0.f ? h : 0.f) * w4.w;
            }
            sum += __shfl_xor_sync(0xffffffffu, sum, 1);
            if ((tid & 1) == 0 && r0 + row < cnt)
                out[(size_t)ridx[row] * 3 + 1] = sum + Cb2[grp];
        }
    }
}

extern "C" void kernel_launch(void* const* d_in, const int* in_sizes, int n_in,
                              void* d_out, int out_size) {
    const float* x = (const float*)d_in[0];
    const int* commands = (const int*)d_in[1];
    const int* tasks = (const int*)d_in[2];
    const int* actions = (const int*)d_in[3];
    const float* A_W1 = (const float*)d_in[4];
    const float* A_b1 = (const float*)d_in[5];
    const float* A_W2 = (const float*)d_in[6];
    const float* A_b2 = (const float*)d_in[7];
    const float* C_W1 = (const float*)d_in[8];
    const float* C_b1 = (const float*)d_in[9];
    const float* C_W2 = (const float*)d_in[10];
    const float* C_b2 = (const float*)d_in[11];
    float* out = (float*)d_out;

    cudaFuncSetAttribute(fused_kernel, cudaFuncAttributeMaxDynamicSharedMemorySize,
                         SMEM_TOTAL);

    zero_kernel<<<1, 32>>>();
    route_kernel<<<Bn / 256, 256>>>(commands, tasks);
    int prep_elems = En * Fn * Hn + En * Hn * An + Tn * Fn * HCn;
    prep_kernel<<<(prep_elems + 255) / 256, 256>>>(A_W1, A_W2, C_W1);
    fused_kernel<<<dim3(NTILES_MAX, 1, 2), 128, SMEM_TOTAL>>>(
        x, actions, A_b1, A_b2, C_b1, C_W2, C_b2, out);
}